// round 15
// baseline (speedup 1.0000x reference)
#include <cuda_runtime.h>
#include <cuda_bf16.h>
#include <cstdint>
#include <math.h>

#define Bx 2
#define Sx 4096
#define Dx 768
#define NHx 12
#define HDx 64
#define BSx 64
#define NBx 64
#define FFx 3072
#define Rx 3
#define NGx 8
#define NMID 62
#define TOK (Bx*Sx)

// ---------------- scratch ----------------
__device__ float g_h[(size_t)TOK*Dx];
__device__ float g_res[(size_t)TOK*Dx];
__device__ float g_ctx[(size_t)TOK*Dx];
__device__ float g_ff[(size_t)TOK*FFx];
__device__ float g_wt[(size_t)Dx*FFx];
__device__ float g_q[(size_t)TOK*Dx];
__device__ float g_k[(size_t)TOK*Dx];
__device__ float g_v[(size_t)TOK*Dx];
__device__ float g_sedge[(size_t)Bx*NHx*2*BSx*Sx];

// ---------------- helpers ----------------
__device__ __forceinline__ float rna_tf32(float x) {
    uint32_t o;
    asm("cvt.rna.tf32.f32 %0, %1;" : "=r"(o) : "f"(x));
    return __uint_as_float(o);
}
__device__ __forceinline__ float fexp(float x) {
    x = fmaxf(x, -80.f);
    float t = fmaf(x, 1.4426950408889634f, 12582912.0f);
    float i = t - 12582912.0f;
    float f = fmaf(x, 1.4426950408889634f, -i);
    float pr = 1.5403530e-4f;
    pr = fmaf(pr, f, 1.3333558e-3f);
    pr = fmaf(pr, f, 9.6181291e-3f);
    pr = fmaf(pr, f, 5.5504109e-2f);
    pr = fmaf(pr, f, 2.4022651e-1f);
    pr = fmaf(pr, f, 6.9314718e-1f);
    pr = fmaf(pr, f, 1.0f);
    int ii = (int)i;
    float sc = __int_as_float((ii + 127) << 23);
    return pr * sc;
}

__device__ __forceinline__ float blk_sum(float v) {
    __shared__ float red[33];
    #pragma unroll
    for (int o = 16; o; o >>= 1) v += __shfl_down_sync(0xffffffffu, v, o);
    int lane = threadIdx.x & 31, w = threadIdx.x >> 5;
    __syncthreads();
    if (lane == 0) red[w] = v;
    __syncthreads();
    if (w == 0) {
        float x = (lane < ((blockDim.x + 31) >> 5)) ? red[lane] : 0.f;
        #pragma unroll
        for (int o = 16; o; o >>= 1) x += __shfl_down_sync(0xffffffffu, x, o);
        if (lane == 0) red[32] = x;
    }
    __syncthreads();
    return red[32];
}

__device__ __forceinline__ float blk_max(float v) {
    __shared__ float redm[33];
    #pragma unroll
    for (int o = 16; o; o >>= 1) v = fmaxf(v, __shfl_down_sync(0xffffffffu, v, o));
    int lane = threadIdx.x & 31, w = threadIdx.x >> 5;
    __syncthreads();
    if (lane == 0) redm[w] = v;
    __syncthreads();
    if (w == 0) {
        float x = (lane < ((blockDim.x + 31) >> 5)) ? redm[lane] : -3.4e38f;
        #pragma unroll
        for (int o = 16; o; o >>= 1) x = fmaxf(x, __shfl_xor_sync(0xffffffffu, x, o));
        if (lane == 0) redm[32] = x;
    }
    __syncthreads();
    return redm[32];
}

// ---------------- weight transpose + tf32 round ----------------
__global__ void trans_round_kernel(const float* __restrict__ in, float* __restrict__ out,
                                   int K, int N) {
    __shared__ float t[32][33];
    int n0 = blockIdx.x * 32, k0 = blockIdx.y * 32;
    int tx = threadIdx.x, ty = threadIdx.y;
    #pragma unroll
    for (int i = ty; i < 32; i += 8) t[i][tx] = in[(size_t)(k0 + i) * N + n0 + tx];
    __syncthreads();
    #pragma unroll
    for (int i = ty; i < 32; i += 8)
        out[(size_t)(n0 + i) * K + k0 + tx] = rna_tf32(t[tx][i]);
}

// ---------------- embeddings + LN ----------------
__global__ void embed_ln_kernel(const int* __restrict__ ids, const int* __restrict__ tt,
                                const float* __restrict__ wemb, const float* __restrict__ temb,
                                const float* __restrict__ pemb,
                                const float* __restrict__ lns, const float* __restrict__ lnb) {
    int tok = blockIdx.x;
    int pos = tok % Sx;
    const float* w = wemb + (size_t)ids[tok] * Dx;
    const float* t = temb + (size_t)tt[tok] * Dx;
    const float* p = pemb + (size_t)pos * Dx;
    __shared__ float buf[Dx];
    float ls = 0.f, lq = 0.f;
    for (int i = threadIdx.x; i < Dx; i += blockDim.x) {
        float x = w[i] + t[i] + p[i];
        buf[i] = x; ls += x; lq += x * x;
    }
    float sum = blk_sum(ls);
    float sq  = blk_sum(lq);
    float mu = sum * (1.f / Dx);
    float var = sq * (1.f / Dx) - mu * mu;
    float inv = rsqrtf(var + 1e-12f);
    for (int i = threadIdx.x; i < Dx; i += blockDim.x) {
        float y = lns[i] * (buf[i] - mu) * inv + lnb[i];
        g_h[(size_t)tok * Dx + i] = rna_tf32(y);
    }
}

__global__ void add_ln_kernel(float* __restrict__ h, const float* __restrict__ r,
                              const float* __restrict__ lns, const float* __restrict__ lnb) {
    int tok = blockIdx.x;
    __shared__ float buf[Dx];
    float ls = 0.f, lq = 0.f;
    for (int i = threadIdx.x; i < Dx; i += blockDim.x) {
        float x = h[(size_t)tok * Dx + i] + r[(size_t)tok * Dx + i];
        buf[i] = x; ls += x; lq += x * x;
    }
    float sum = blk_sum(ls);
    float sq  = blk_sum(lq);
    float mu = sum * (1.f / Dx);
    float var = sq * (1.f / Dx) - mu * mu;
    float inv = rsqrtf(var + 1e-12f);
    for (int i = threadIdx.x; i < Dx; i += blockDim.x) {
        float y = lns[i] * (buf[i] - mu) * inv + lnb[i];
        h[(size_t)tok * Dx + i] = rna_tf32(y);
    }
}

// ---------------- MMA primitives ----------------
__device__ __forceinline__ void ldsm_x4(uint32_t* r, uint32_t addr) {
    asm volatile("ldmatrix.sync.aligned.m8n8.x4.shared.b16 {%0,%1,%2,%3}, [%4];"
                 : "=r"(r[0]), "=r"(r[1]), "=r"(r[2]), "=r"(r[3]) : "r"(addr));
}
__device__ __forceinline__ void mma_tf32(float* c, const uint32_t* a, uint32_t b0, uint32_t b1) {
    asm volatile("mma.sync.aligned.m16n8k8.row.col.f32.tf32.tf32.f32 "
                 "{%0,%1,%2,%3}, {%4,%5,%6,%7}, {%8,%9}, {%0,%1,%2,%3};"
                 : "+f"(c[0]), "+f"(c[1]), "+f"(c[2]), "+f"(c[3])
                 : "r"(a[0]), "r"(a[1]), "r"(a[2]), "r"(a[3]), "r"(b0), "r"(b1));
}
__device__ __forceinline__ void cp16(void* dst, const void* src) {
    uint32_t d = (uint32_t)__cvta_generic_to_shared(dst);
    asm volatile("cp.async.cg.shared.global [%0], [%1], 16;" :: "r"(d), "l"(src));
}

// ---------------- TF32 dense GEMM ----------------
#define TF_STRIDE 36
#define TF_STAGE (128 * TF_STRIDE * 2)
#define TF_OFF_B (128 * TF_STRIDE)
#define TF_SMEM_BYTES (2 * TF_STAGE * 4)

__device__ __forceinline__ void tf_load_stage(
    float* sm, int s, int k0, int tid, int m0, int n0,
    const float* __restrict__ A, const float* __restrict__ Bt, int K)
{
    float* st = sm + s * TF_STAGE;
    #pragma unroll
    for (int i = 0; i < 4; i++) {
        int idx = tid + i * 256;
        int r = idx >> 3, c = (idx & 7) * 4;
        cp16(st + r * TF_STRIDE + c, A + (size_t)(m0 + r) * K + k0 + c);
        cp16(st + TF_OFF_B + r * TF_STRIDE + c, Bt + (size_t)(n0 + r) * K + k0 + c);
    }
    asm volatile("cp.async.commit_group;");
}

template<int MODE>
__device__ __forceinline__ void tf_gemm_body(
    const float* __restrict__ A, const float* __restrict__ Bt,
    const float* __restrict__ bias, float* __restrict__ C,
    int M, int N, int K, int bxb, int byb, float* sm)
{
    const int tid = threadIdx.x;
    const int lane = tid & 31;
    const int wid = tid >> 5;
    const int warp_m = wid & 3;
    const int warp_n = wid >> 2;
    const int m0 = byb * 128;
    const int n0 = bxb * 128;

    float acc[2][8][4];
    #pragma unroll
    for (int mt = 0; mt < 2; mt++) {
        #pragma unroll
        for (int nt = 0; nt < 8; nt++) {
            acc[mt][nt][0] = 0.f; acc[mt][nt][1] = 0.f;
            acc[mt][nt][2] = 0.f; acc[mt][nt][3] = 0.f;
        }
    }

    const int phase = lane >> 3;
    const int rli = lane & 7;
    const int a_roff = (phase & 1) * 8 + rli;
    const int a_koff = (phase >> 1) * 4;
    const int b_roff = (phase >> 1) * 8 + rli;
    const int b_koff = (phase & 1) * 4;

    const int nk = K >> 5;
    tf_load_stage(sm, 0, 0, tid, m0, n0, A, Bt, K);

    for (int kt = 0; kt < nk; kt++) {
        const int s = kt & 1;
        asm volatile("cp.async.wait_group 0;");
        __syncthreads();
        if (kt + 1 < nk)
            tf_load_stage(sm, s ^ 1, (kt + 1) * 32, tid, m0, n0, A, Bt, K);

        float* stA = sm + s * TF_STAGE;
        float* stB = stA + TF_OFF_B;

        #pragma unroll
        for (int kk = 0; kk < 32; kk += 8) {
            uint32_t aa0[4], aa1[4];
            ldsm_x4(aa0, (uint32_t)__cvta_generic_to_shared(
                stA + (warp_m * 32 + a_roff) * TF_STRIDE + kk + a_koff));
            ldsm_x4(aa1, (uint32_t)__cvta_generic_to_shared(
                stA + (warp_m * 32 + 16 + a_roff) * TF_STRIDE + kk + a_koff));
            #pragma unroll
            for (int p = 0; p < 4; p++) {
                uint32_t bb[4];
                ldsm_x4(bb, (uint32_t)__cvta_generic_to_shared(
                    stB + (warp_n * 64 + p * 16 + b_roff) * TF_STRIDE + kk + b_koff));
                int nt0 = p * 2;
                int nt1 = p * 2 + 1;
                mma_tf32(acc[0][nt0], aa0, bb[0], bb[1]);
                mma_tf32(acc[0][nt1], aa0, bb[2], bb[3]);
                mma_tf32(acc[1][nt0], aa1, bb[0], bb[1]);
                mma_tf32(acc[1][nt1], aa1, bb[2], bb[3]);
            }
        }
    }

    const int grp = lane >> 2;
    const int tig = lane & 3;
    #pragma unroll
    for (int mt = 0; mt < 2; mt++) {
        #pragma unroll
        for (int nt = 0; nt < 8; nt++) {
            int col = n0 + warp_n * 64 + nt * 8 + tig * 2;
            float b0 = bias[col];
            float b1 = bias[col + 1];
            #pragma unroll
            for (int half = 0; half < 2; half++) {
                int row = m0 + warp_m * 32 + mt * 16 + grp + half * 8;
                float v0 = acc[mt][nt][half * 2 + 0] + b0;
                float v1 = acc[mt][nt][half * 2 + 1] + b1;
                if (MODE == 3) {
                    v0 = 0.5f * v0 * (1.f + erff(v0 * 0.70710678118654752f));
                    v1 = 0.5f * v1 * (1.f + erff(v1 * 0.70710678118654752f));
                }
                if (MODE == 3 || MODE == 4) {
                    C[(size_t)row * N + col]     = rna_tf32(v0);
                    C[(size_t)row * N + col + 1] = rna_tf32(v1);
                } else {
                    C[(size_t)row * N + col]     = v0;
                    C[(size_t)row * N + col + 1] = v1;
                }
            }
        }
    }
}

template<int MODE>
__global__ void __launch_bounds__(256, 2) tf_gemm_kernel(
    const float* __restrict__ A, const float* __restrict__ Bt,
    const float* __restrict__ bias, float* __restrict__ C,
    int M, int N, int K)
{
    extern __shared__ __align__(16) float sm[];
    tf_gemm_body<MODE>(A, Bt, bias, C, M, N, K, blockIdx.x, blockIdx.y, sm);
}

__global__ void __launch_bounds__(256, 2) tf_qkv_kernel(
    const float* __restrict__ A, const float* __restrict__ Bt,
    const float* __restrict__ bq, const float* __restrict__ bk, const float* __restrict__ bv,
    float* __restrict__ q, float* __restrict__ k, float* __restrict__ v)
{
    extern __shared__ __align__(16) float sm[];
    int z = blockIdx.z;
    size_t woff = (size_t)z * Dx * Dx;
    const float* bias = (z == 0) ? bq : (z == 1) ? bk : bv;
    float* C = (z == 0) ? q : (z == 1) ? k : v;
    tf_gemm_body<4>(A, Bt + woff, bias, C, TOK, Dx, Dx, blockIdx.x, blockIdx.y, sm);
}

// ---------------- attention helpers ----------------
__device__ __forceinline__ int mid_block_idx(int n, int g, const int* __restrict__ randb) {
    if (g == 0) return 0;
    if (g == 1) return NBx - 1;
    if (g < 5)  return n - 3 + g;
    return randb[(n - 1) * Rx + (g - 5)];
}

#define FT_STRIDE 68
__device__ __forceinline__ void load_ftile(
    float (*dst)[FT_STRIDE], const float* __restrict__ src, int gstride, int tid)
{
    #pragma unroll
    for (int i = 0; i < 4; i++) {
        int idx = tid + i * 256;
        int r = idx >> 4, c = (idx & 15) * 4;
        *(float4*)&dst[r][c] = *(const float4*)(src + (size_t)r * gstride + c);
    }
}
__device__ __forceinline__ void load_ftile32(
    float (*dst)[FT_STRIDE], const float* __restrict__ src, int gstride, int tid)
{
    #pragma unroll
    for (int i = 0; i < 2; i++) {
        int idx = tid + i * 256;
        int r = idx >> 4, c = (idx & 15) * 4;
        *(float4*)&dst[r][c] = *(const float4*)(src + (size_t)r * gstride + c);
    }
}

// ---------------- fused middle-block attention (tf32, 32 q-rows / CTA) ----------
#define SROW 516
#define MID_SMEM (32 * SROW * 4 + 32 * FT_STRIDE * 4 + 64 * FT_STRIDE * 4)

__global__ void __launch_bounds__(256, 2) mid_fused_kernel(
    const float* __restrict__ q, const float* __restrict__ k, const float* __restrict__ v,
    const int* __restrict__ randb, const int* __restrict__ amask,
    float* __restrict__ ctx)
{
    extern __shared__ __align__(16) char smraw[];
    float (*Sf)[SROW] = (float(*)[SROW])smraw;
    float (*Qs)[FT_STRIDE] = (float(*)[FT_STRIDE])(smraw + 32 * SROW * 4);
    float (*Ks)[FT_STRIDE] = (float(*)[FT_STRIDE])(smraw + 32 * SROW * 4 + 32 * FT_STRIDE * 4);

    int n = blockIdx.x + 1, h = blockIdx.y;
    int b = blockIdx.z >> 1, half = blockIdx.z & 1;
    int tid = threadIdx.x, lane = tid & 31, wid = tid >> 5;
    int warp_m = wid & 1, warp_n = wid >> 1;   // 2 m-tiles x 4 key/d-groups of 16

    const int phase = lane >> 3;
    const int rli = lane & 7;
    const int a_roff = (phase & 1) * 8 + rli;
    const int a_koff = (phase >> 1) * 4;
    const int b_roff = (phase >> 1) * 8 + rli;
    const int b_koff = (phase & 1) * 4;

    int qrow0 = n * 64 + half * 32;
    size_t qoff = ((size_t)b * Sx + qrow0) * Dx + h * 64;
    load_ftile32(Qs, q + qoff, Dx, tid);

    // --- phase 1: scores ---
    for (int g = 0; g < NGx; g++) {
        int kb = mid_block_idx(n, g, randb);
        size_t koff = ((size_t)b * Sx + kb * 64) * Dx + h * 64;
        __syncthreads();
        load_ftile(Ks, k + koff, Dx, tid);
        __syncthreads();

        float acc[2][4];
        #pragma unroll
        for (int j = 0; j < 2; j++) {
            acc[j][0] = 0.f; acc[j][1] = 0.f; acc[j][2] = 0.f; acc[j][3] = 0.f;
        }
        #pragma unroll
        for (int kk = 0; kk < 64; kk += 8) {
            uint32_t aa[4];
            ldsm_x4(aa, (uint32_t)__cvta_generic_to_shared(
                &Qs[warp_m * 16 + a_roff][kk + a_koff]));
            uint32_t bb[4];
            ldsm_x4(bb, (uint32_t)__cvta_generic_to_shared(
                &Ks[warp_n * 16 + b_roff][kk + b_koff]));
            mma_tf32(acc[0], aa, bb[0], bb[1]);
            mma_tf32(acc[1], aa, bb[2], bb[3]);
        }

        int r0 = warp_m * 16 + (lane >> 2);
        int mask_base = b * Sx + kb * 64;
        #pragma unroll
        for (int j = 0; j < 2; j++) {
            int ki = warp_n * 16 + j * 8 + (lane & 3) * 2;
            float m0 = (1.0f - (float)amask[mask_base + ki]) * -1e9f;
            float m1 = (1.0f - (float)amask[mask_base + ki + 1]) * -1e9f;
            Sf[r0][g * 64 + ki]           = acc[j][0] * 0.125f + m0;
            Sf[r0][g * 64 + ki + 1]       = acc[j][1] * 0.125f + m1;
            Sf[r0 + 8][g * 64 + ki]       = acc[j][2] * 0.125f + m0;
            Sf[r0 + 8][g * 64 + ki + 1]   = acc[j][3] * 0.125f + m1;
        }
    }
    __syncthreads();

    // --- phase 2: softmax (32 rows, 4 per warp) ---
    for (int rr = 0; rr < 4; rr++) {
        int row = wid * 4 + rr;
        float vv[16];
        float m = -3.4e38f;
        #pragma unroll
        for (int j = 0; j < 16; j++) {
            vv[j] = Sf[row][lane + 32 * j];
            m = fmaxf(m, vv[j]);
        }
        #pragma unroll
        for (int o = 16; o; o >>= 1) m = fmaxf(m, __shfl_xor_sync(0xffffffffu, m, o));
        float s = 0.f;
        #pragma unroll
        for (int j = 0; j < 16; j++) { vv[j] = fexp(vv[j] - m); s += vv[j]; }
        #pragma unroll
        for (int o = 16; o; o >>= 1) s += __shfl_xor_sync(0xffffffffu, s, o);
        float inv = 1.f / s;
        #pragma unroll
        for (int j = 0; j < 16; j++) Sf[row][lane + 32 * j] = rna_tf32(vv[j] * inv);
    }
    __syncthreads();

    // --- phase 3: PV ---
    float acc[2][4];
    #pragma unroll
    for (int j = 0; j < 2; j++) {
        acc[j][0] = 0.f; acc[j][1] = 0.f; acc[j][2] = 0.f; acc[j][3] = 0.f;
    }
    const int ck = lane & 3;
    const int nr = lane >> 2;
    for (int g = 0; g < NGx; g++) {
        int kb = mid_block_idx(n, g, randb);
        size_t voff = ((size_t)b * Sx + kb * 64) * Dx + h * 64;
        __syncthreads();
        load_ftile(Ks, v + voff, Dx, tid);
        __syncthreads();
        #pragma unroll
        for (int kk = 0; kk < 64; kk += 8) {
            uint32_t aa[4];
            ldsm_x4(aa, (uint32_t)__cvta_generic_to_shared(
                &Sf[warp_m * 16 + a_roff][g * 64 + kk + a_koff]));
            #pragma unroll
            for (int j = 0; j < 2; j++) {
                int n0 = warp_n * 16 + j * 8 + nr;
                uint32_t b0 = __float_as_uint(Ks[kk + ck][n0]);
                uint32_t b1 = __float_as_uint(Ks[kk + 4 + ck][n0]);
                mma_tf32(acc[j], aa, b0, b1);
            }
        }
    }

    float* cbase = ctx + ((size_t)b * Sx + qrow0) * Dx + h * 64;
    int pr = warp_m * 16 + (lane >> 2);
    #pragma unroll
    for (int j = 0; j < 2; j++) {
        int col = warp_n * 16 + j * 8 + (lane & 3) * 2;
        cbase[(size_t)pr * Dx + col]           = rna_tf32(acc[j][0]);
        cbase[(size_t)pr * Dx + col + 1]       = rna_tf32(acc[j][1]);
        cbase[(size_t)(pr + 8) * Dx + col]     = rna_tf32(acc[j][2]);
        cbase[(size_t)(pr + 8) * Dx + col + 1] = rna_tf32(acc[j][3]);
    }
}

// ---------------- edge scores (tf32) ----------------
__device__ __forceinline__ void score_tile_tf(
    const float (*Qs)[FT_STRIDE], const float (*Ks)[FT_STRIDE],
    float acc[4][4], int lane, int warp_m, int warp_n)
{
    const int phase = lane >> 3;
    const int rli = lane & 7;
    const int a_roff = (phase & 1) * 8 + rli;
    const int a_koff = (phase >> 1) * 4;
    const int b_roff = (phase >> 1) * 8 + rli;
    const int b_koff = (phase & 1) * 4;

    #pragma unroll
    for (int kk = 0; kk < 64; kk += 8) {
        uint32_t aa[4];
        ldsm_x4(aa, (uint32_t)__cvta_generic_to_shared(
            &Qs[warp_m * 16 + a_roff][kk + a_koff]));
        #pragma unroll
        for (int p = 0; p < 2; p++) {
            uint32_t bb[4];
            ldsm_x4(bb, (uint32_t)__cvta_generic_to_shared(
                &Ks[warp_n * 32 + p * 16 + b_roff][kk + b_koff]));
            mma_tf32(acc[p * 2 + 0], aa, bb[0], bb[1]);
            mma_tf32(acc[p * 2 + 1], aa, bb[2], bb[3]);
        }
    }
}

__device__ __forceinline__ void pv_tile_tf(
    const float* __restrict__ P, int pstride, int pcol0,
    const float (*Vs)[FT_STRIDE],
    float acc[4][4], int lane, int warp_m, int warp_n)
{
    const int phase = lane >> 3;
    const int rli = lane & 7;
    const int a_roff = (phase & 1) * 8 + rli;
    const int a_koff = (phase >> 1) * 4;
    const int ck = lane & 3;
    const int nr = lane >> 2;

    #pragma unroll
    for (int kk = 0; kk < 64; kk += 8) {
        uint32_t aa[4];
        ldsm_x4(aa, (uint32_t)__cvta_generic_to_shared(
            P + (size_t)(warp_m * 16 + a_roff) * pstride + pcol0 + kk + a_koff));
        #pragma unroll
        for (int j = 0; j < 4; j++) {
            int n0 = warp_n * 32 + j * 8 + nr;
            uint32_t b0 = __float_as_uint(Vs[kk + ck][n0]);
            uint32_t b1 = __float_as_uint(Vs[kk + 4 + ck][n0]);
            mma_tf32(acc[j], aa, b0, b1);
        }
    }
}

__global__ void __launch_bounds__(256) edge_scores_tf(
    const float* __restrict__ q, const float* __restrict__ k,
    const int* __restrict__ amask, float* __restrict__ sedge)
{
    int kb = blockIdx.x, h = blockIdx.y;
    int e = blockIdx.z & 1, b = blockIdx.z >> 1;
    int qb = e ? (NBx - 1) : 0;
    __shared__ float Qs[64][FT_STRIDE];
    __shared__ float Ks[64][FT_STRIDE];
    int tid = threadIdx.x, lane = tid & 31, wid = tid >> 5;
    int warp_m = wid & 3, warp_n = wid >> 2;

    size_t qoff = ((size_t)b * Sx + qb * 64) * Dx + h * 64;
    size_t koff = ((size_t)b * Sx + kb * 64) * Dx + h * 64;
    load_ftile(Qs, q + qoff, Dx, tid);
    load_ftile(Ks, k + koff, Dx, tid);
    __syncthreads();

    float acc[4][4];
    #pragma unroll
    for (int j = 0; j < 4; j++) {
        acc[j][0] = 0.f; acc[j][1] = 0.f; acc[j][2] = 0.f; acc[j][3] = 0.f;
    }
    score_tile_tf(Qs, Ks, acc, lane, warp_m, warp_n);

    float* out = sedge + ((size_t)((b * NHx + h) * 2 + e)) * (64 * Sx);
    int r0 = warp_m * 16 + (lane >> 2);
    int mask_base = b * Sx + kb * 64;
    #pragma unroll
    for (int j = 0; j < 4; j++) {
        int ki = warp_n * 32 + j * 8 + (lane & 3) * 2;
        float m0 = (1.0f - (float)amask[mask_base + ki]) * -1e9f;
        float m1 = (1.0f - (float)amask[mask_base + ki + 1]) * -1e9f;
        out[(size_t)r0 * Sx + kb * 64 + ki]           = acc[j][0] * 0.125f + m0;
        out[(size_t)r0 * Sx + kb * 64 + ki + 1]       = acc[j][1] * 0.125f + m1;
        out[(size_t)(r0 + 8) * Sx + kb * 64 + ki]     = acc[j][2] * 0.125f + m0;
        out[(size_t)(r0 + 8) * Sx + kb * 64 + ki + 1] = acc[j][3] * 0.125f + m1;
    }
}

// ---------------- edge softmax in place (rna) ----------------
__global__ void softmax_rna_kernel(float* __restrict__ s, int L) {
    extern __shared__ float buf[];
    size_t base = (size_t)blockIdx.x * L;
    float m = -3.4e38f;
    for (int i = threadIdx.x; i < L; i += blockDim.x) {
        float x = s[base + i];
        buf[i] = x;
        m = fmaxf(m, x);
    }
    m = blk_max(m);
    float lsum = 0.f;
    for (int i = threadIdx.x; i < L; i += blockDim.x) {
        float e = fexp(buf[i] - m);
        buf[i] = e;
        lsum += e;
    }
    float sum = blk_sum(lsum);
    float inv = 1.f / sum;
    for (int i = threadIdx.x; i < L; i += blockDim.x)
        s[base + i] = rna_tf32(buf[i] * inv);
}

// ---------------- edge PV (tf32, chunked atomic) ----------------
__global__ void __launch_bounds__(256) edge_pv_tf(
    const float* __restrict__ p, const float* __restrict__ v, float* __restrict__ ctx)
{
    int h = blockIdx.x;
    int e = blockIdx.y & 1, b = blockIdx.y >> 1;
    int chunk = blockIdx.z;
    int qb = e ? (NBx - 1) : 0;
    __shared__ float Ps[64][FT_STRIDE];
    __shared__ float Vs[64][FT_STRIDE];
    int tid = threadIdx.x, lane = tid & 31, wid = tid >> 5;
    int warp_m = wid & 3, warp_n = wid >> 2;

    const float* prow = p + ((size_t)((b * NHx + h) * 2 + e)) * (64 * Sx);

    float acc[4][4];
    #pragma unroll
    for (int j = 0; j < 4; j++) {
        acc[j][0] = 0.f; acc[j][1] = 0.f; acc[j][2] = 0.f; acc[j][3] = 0.f;
    }

    for (int c8 = 0; c8 < 8; c8++) {
        int kb = chunk * 8 + c8;
        size_t voff = ((size_t)b * Sx + kb * 64) * Dx + h * 64;
        __syncthreads();
        load_ftile(Ps, prow + kb * 64, Sx, tid);
        load_ftile(Vs, v + voff, Dx, tid);
        __syncthreads();
        pv_tile_tf(&Ps[0][0], FT_STRIDE, 0, Vs, acc, lane, warp_m, warp_n);
    }

    float* cbase = ctx + ((size_t)b * Sx + qb * 64) * Dx + h * 64;
    int r0 = warp_m * 16 + (lane >> 2);
    #pragma unroll
    for (int j = 0; j < 4; j++) {
        int col = warp_n * 32 + j * 8 + (lane & 3) * 2;
        atomicAdd(&cbase[(size_t)r0 * Dx + col],           acc[j][0]);
        atomicAdd(&cbase[(size_t)r0 * Dx + col + 1],       acc[j][1]);
        atomicAdd(&cbase[(size_t)(r0 + 8) * Dx + col],     acc[j][2]);
        atomicAdd(&cbase[(size_t)(r0 + 8) * Dx + col + 1], acc[j][3]);
    }
}

__global__ void zero_edge_ctx(float* __restrict__ ctx) {
    int i = blockIdx.x * 256 + threadIdx.x;
    if (i >= Bx * 2 * 64 * Dx) return;
    int col = i % Dx;
    int t = i / Dx;
    int row = t % 64;  t /= 64;
    int e = t & 1;
    int b = t >> 1;
    int blk = e ? (NBx - 1) : 0;
    ctx[((size_t)b * Sx + blk * 64 + row) * Dx + col] = 0.f;
}

// ---------------- pooler ----------------
__global__ void pooler_kernel(const float* __restrict__ h, const float* __restrict__ pw,
                              const float* __restrict__ pb, float* __restrict__ out) {
    int j = blockIdx.x * blockDim.x + threadIdx.x;
    int b = blockIdx.y;
    if (j >= Dx) return;
    const float* hr = h + (size_t)b * Sx * Dx;
    float acc = pb[j];
    for (int kI = 0; kI < Dx; kI++) acc += hr[kI] * pw[(size_t)kI * Dx + j];
    out[b * Dx + j] = tanhf(acc);
}

// ---------------- host launcher ----------------
extern "C" void kernel_launch(void* const* d_in, const int* in_sizes, int n_in,
                              void* d_out, int out_size) {
    const int*   input_ids = (const int*)d_in[0];
    const int*   attn_mask = (const int*)d_in[1];
    const int*   tok_type  = (const int*)d_in[2];
    const int*   rand_blk  = (const int*)d_in[3];
    const float* word_emb  = (const float*)d_in[4];
    const float* type_emb  = (const float*)d_in[5];
    const float* pos_emb   = (const float*)d_in[6];
    const float* emb_ln_s  = (const float*)d_in[7];
    const float* emb_ln_b  = (const float*)d_in[8];
    const float* Wq = (const float*)d_in[9];  const float* bq = (const float*)d_in[10];
    const float* Wk = (const float*)d_in[11]; const float* bk = (const float*)d_in[12];
    const float* Wv = (const float*)d_in[13]; const float* bv = (const float*)d_in[14];
    const float* Wo = (const float*)d_in[15]; const float* bo = (const float*)d_in[16];
    const float* ln1_s = (const float*)d_in[17]; const float* ln1_b = (const float*)d_in[18];
    const float* W1 = (const float*)d_in[19]; const float* b1 = (const float*)d_in[20];
    const float* W2 = (const float*)d_in[21]; const float* b2 = (const float*)d_in[22];
    const float* ln2_s = (const float*)d_in[23]; const float* ln2_b = (const float*)d_in[24];
    const float* pool_w = (const float*)d_in[25]; const float* pool_b = (const float*)d_in[26];
    float* out = (float*)d_out;

    float *p_h = 0, *p_res = 0, *p_ctx = 0, *p_ff = 0, *p_wt = 0, *p_sedge = 0;
    float *p_q = 0, *p_k = 0, *p_v = 0;
    cudaGetSymbolAddress((void**)&p_h,     g_h);
    cudaGetSymbolAddress((void**)&p_res,   g_res);
    cudaGetSymbolAddress((void**)&p_ctx,   g_ctx);
    cudaGetSymbolAddress((void**)&p_ff,    g_ff);
    cudaGetSymbolAddress((void**)&p_wt,    g_wt);
    cudaGetSymbolAddress((void**)&p_sedge, g_sedge);
    cudaGetSymbolAddress((void**)&p_q,     g_q);
    cudaGetSymbolAddress((void**)&p_k,     g_k);
    cudaGetSymbolAddress((void**)&p_v,     g_v);

    static bool attr_done = false;
    if (!attr_done) {
        cudaFuncSetAttribute(tf_gemm_kernel<0>, cudaFuncAttributeMaxDynamicSharedMemorySize, TF_SMEM_BYTES);
        cudaFuncSetAttribute(tf_gemm_kernel<3>, cudaFuncAttributeMaxDynamicSharedMemorySize, TF_SMEM_BYTES);
        cudaFuncSetAttribute(tf_qkv_kernel, cudaFuncAttributeMaxDynamicSharedMemorySize, TF_SMEM_BYTES);
        cudaFuncSetAttribute(mid_fused_kernel, cudaFuncAttributeMaxDynamicSharedMemorySize, MID_SMEM);
        attr_done = true;
    }

    const int M = TOK;
    const int nDD = Dx * Dx;

    embed_ln_kernel<<<TOK, 256>>>(input_ids, tok_type, word_emb, type_emb, pos_emb,
                                  emb_ln_s, emb_ln_b);

    for (int l = 0; l < 2; l++) {
        const float* wq = Wq + (size_t)l * nDD;  const float* bql = bq + (size_t)l * Dx;
        const float* wk = Wk + (size_t)l * nDD;  const float* bkl = bk + (size_t)l * Dx;
        const float* wv = Wv + (size_t)l * nDD;  const float* bvl = bv + (size_t)l * Dx;
        const float* wo = Wo + (size_t)l * nDD;  const float* bol = bo + (size_t)l * Dx;
        const float* w1 = W1 + (size_t)l * Dx * FFx; const float* b1l = b1 + (size_t)l * FFx;
        const float* w2 = W2 + (size_t)l * Dx * FFx; const float* b2l = b2 + (size_t)l * Dx;
        const float* l1s = ln1_s + (size_t)l * Dx; const float* l1b = ln1_b + (size_t)l * Dx;
        const float* l2s = ln2_s + (size_t)l * Dx; const float* l2b = ln2_b + (size_t)l * Dx;

        // QKV (tf32)
        trans_round_kernel<<<dim3(Dx / 32, Dx / 32), dim3(32, 8)>>>(wq, p_wt,           Dx, Dx);
        trans_round_kernel<<<dim3(Dx / 32, Dx / 32), dim3(32, 8)>>>(wk, p_wt + nDD,     Dx, Dx);
        trans_round_kernel<<<dim3(Dx / 32, Dx / 32), dim3(32, 8)>>>(wv, p_wt + 2 * nDD, Dx, Dx);
        tf_qkv_kernel<<<dim3(Dx / 128, M / 128, 3), 256, TF_SMEM_BYTES>>>(
            p_h, p_wt, bql, bkl, bvl, p_q, p_k, p_v);

        // middle blocks: fused scores+softmax+PV (tf32, 32 q-rows/CTA, 2 CTAs/SM)
        mid_fused_kernel<<<dim3(NMID, NHx, Bx * 2), 256, MID_SMEM>>>(
            p_q, p_k, p_v, rand_blk, attn_mask, p_ctx);

        // edge blocks (tf32)
        edge_scores_tf<<<dim3(NBx, NHx, Bx * 2), 256>>>(p_q, p_k, attn_mask, p_sedge);
        softmax_rna_kernel<<<Bx * NHx * 2 * BSx, 256, Sx * sizeof(float)>>>(p_sedge, Sx);
        zero_edge_ctx<<<(Bx * 2 * 64 * Dx + 255) / 256, 256>>>(p_ctx);
        edge_pv_tf<<<dim3(NHx, Bx * 2, 8), 256>>>(p_sedge, p_v, p_ctx);

        // O-projection (tf32) + LN
        trans_round_kernel<<<dim3(Dx / 32, Dx / 32), dim3(32, 8)>>>(wo, p_wt, Dx, Dx);
        tf_gemm_kernel<0><<<dim3(Dx / 128, M / 128), 256, TF_SMEM_BYTES>>>(
            p_ctx, p_wt, bol, p_res, M, Dx, Dx);
        add_ln_kernel<<<TOK, 256>>>(p_h, p_res, l1s, l1b);

        // FFN (tf32)
        trans_round_kernel<<<dim3(FFx / 32, Dx / 32), dim3(32, 8)>>>(w1, p_wt, Dx, FFx);
        tf_gemm_kernel<3><<<dim3(FFx / 128, M / 128), 256, TF_SMEM_BYTES>>>(
            p_h, p_wt, b1l, p_ff, M, FFx, Dx);
        trans_round_kernel<<<dim3(Dx / 32, FFx / 32), dim3(32, 8)>>>(w2, p_wt, FFx, Dx);
        tf_gemm_kernel<0><<<dim3(Dx / 128, M / 128), 256, TF_SMEM_BYTES>>>(
            p_ff, p_wt, b2l, p_res, M, Dx, FFx);
        add_ln_kernel<<<TOK, 256>>>(p_h, p_res, l2s, l2b);
    }

    pooler_kernel<<<dim3((Dx + 127) / 128, Bx), 128>>>(p_h, pool_w, pool_b, out);
}

// round 16
// speedup vs baseline: 1.0065x; 1.0065x over previous
#include <cuda_runtime.h>
#include <cuda_bf16.h>
#include <cstdint>
#include <math.h>

#define Bx 2
#define Sx 4096
#define Dx 768
#define NHx 12
#define HDx 64
#define BSx 64
#define NBx 64
#define FFx 3072
#define Rx 3
#define NGx 8
#define NMID 62
#define TOK (Bx*Sx)
#define nDD (Dx*Dx)
#define nDF (Dx*FFx)

// ---------------- scratch ----------------
__device__ float g_h[(size_t)TOK*Dx];
__device__ float g_res[(size_t)TOK*Dx];
__device__ float g_ctx[(size_t)TOK*Dx];
__device__ float g_ff[(size_t)TOK*FFx];
__device__ float g_wt[(size_t)8*nDD + (size_t)4*nDF];
__device__ float g_q[(size_t)TOK*Dx];
__device__ float g_k[(size_t)TOK*Dx];
__device__ float g_v[(size_t)TOK*Dx];
__device__ float g_sedge[(size_t)Bx*NHx*2*BSx*Sx];

// ---------------- helpers ----------------
__device__ __forceinline__ float rna_tf32(float x) {
    uint32_t o;
    asm("cvt.rna.tf32.f32 %0, %1;" : "=r"(o) : "f"(x));
    return __uint_as_float(o);
}
__device__ __forceinline__ float fexp(float x) {
    x = fmaxf(x, -80.f);
    float t = fmaf(x, 1.4426950408889634f, 12582912.0f);
    float i = t - 12582912.0f;
    float f = fmaf(x, 1.4426950408889634f, -i);
    float pr = 1.5403530e-4f;
    pr = fmaf(pr, f, 1.3333558e-3f);
    pr = fmaf(pr, f, 9.6181291e-3f);
    pr = fmaf(pr, f, 5.5504109e-2f);
    pr = fmaf(pr, f, 2.4022651e-1f);
    pr = fmaf(pr, f, 6.9314718e-1f);
    pr = fmaf(pr, f, 1.0f);
    int ii = (int)i;
    float sc = __int_as_float((ii + 127) << 23);
    return pr * sc;
}

__device__ __forceinline__ float blk_sum(float v) {
    __shared__ float red[33];
    #pragma unroll
    for (int o = 16; o; o >>= 1) v += __shfl_down_sync(0xffffffffu, v, o);
    int lane = threadIdx.x & 31, w = threadIdx.x >> 5;
    __syncthreads();
    if (lane == 0) red[w] = v;
    __syncthreads();
    if (w == 0) {
        float x = (lane < ((blockDim.x + 31) >> 5)) ? red[lane] : 0.f;
        #pragma unroll
        for (int o = 16; o; o >>= 1) x += __shfl_down_sync(0xffffffffu, x, o);
        if (lane == 0) red[32] = x;
    }
    __syncthreads();
    return red[32];
}

__device__ __forceinline__ float blk_max(float v) {
    __shared__ float redm[33];
    #pragma unroll
    for (int o = 16; o; o >>= 1) v = fmaxf(v, __shfl_down_sync(0xffffffffu, v, o));
    int lane = threadIdx.x & 31, w = threadIdx.x >> 5;
    __syncthreads();
    if (lane == 0) redm[w] = v;
    __syncthreads();
    if (w == 0) {
        float x = (lane < ((blockDim.x + 31) >> 5)) ? redm[lane] : -3.4e38f;
        #pragma unroll
        for (int o = 16; o; o >>= 1) x = fmaxf(x, __shfl_xor_sync(0xffffffffu, x, o));
        if (lane == 0) redm[32] = x;
    }
    __syncthreads();
    return redm[32];
}

// ---------------- weight transpose + tf32 round (z-batched) ----------------
__global__ void trans_round_kernel(const float* __restrict__ in, float* __restrict__ out,
                                   int K, int N, size_t zin, size_t zout) {
    __shared__ float t[32][33];
    in  += (size_t)blockIdx.z * zin;
    out += (size_t)blockIdx.z * zout;
    int n0 = blockIdx.x * 32, k0 = blockIdx.y * 32;
    int tx = threadIdx.x, ty = threadIdx.y;
    #pragma unroll
    for (int i = ty; i < 32; i += 8) t[i][tx] = in[(size_t)(k0 + i) * N + n0 + tx];
    __syncthreads();
    #pragma unroll
    for (int i = ty; i < 32; i += 8)
        out[(size_t)(n0 + i) * K + k0 + tx] = rna_tf32(t[tx][i]);
}

// ---------------- embeddings + LN ----------------
__global__ void embed_ln_kernel(const int* __restrict__ ids, const int* __restrict__ tt,
                                const float* __restrict__ wemb, const float* __restrict__ temb,
                                const float* __restrict__ pemb,
                                const float* __restrict__ lns, const float* __restrict__ lnb) {
    int tok = blockIdx.x;
    int pos = tok % Sx;
    const float* w = wemb + (size_t)ids[tok] * Dx;
    const float* t = temb + (size_t)tt[tok] * Dx;
    const float* p = pemb + (size_t)pos * Dx;
    __shared__ float buf[Dx];
    float ls = 0.f, lq = 0.f;
    for (int i = threadIdx.x; i < Dx; i += blockDim.x) {
        float x = w[i] + t[i] + p[i];
        buf[i] = x; ls += x; lq += x * x;
    }
    float sum = blk_sum(ls);
    float sq  = blk_sum(lq);
    float mu = sum * (1.f / Dx);
    float var = sq * (1.f / Dx) - mu * mu;
    float inv = rsqrtf(var + 1e-12f);
    for (int i = threadIdx.x; i < Dx; i += blockDim.x) {
        float y = lns[i] * (buf[i] - mu) * inv + lnb[i];
        g_h[(size_t)tok * Dx + i] = rna_tf32(y);
    }
}

__global__ void add_ln_kernel(float* __restrict__ h, const float* __restrict__ r,
                              const float* __restrict__ lns, const float* __restrict__ lnb) {
    int tok = blockIdx.x;
    __shared__ float buf[Dx];
    float ls = 0.f, lq = 0.f;
    for (int i = threadIdx.x; i < Dx; i += blockDim.x) {
        float x = h[(size_t)tok * Dx + i] + r[(size_t)tok * Dx + i];
        buf[i] = x; ls += x; lq += x * x;
    }
    float sum = blk_sum(ls);
    float sq  = blk_sum(lq);
    float mu = sum * (1.f / Dx);
    float var = sq * (1.f / Dx) - mu * mu;
    float inv = rsqrtf(var + 1e-12f);
    for (int i = threadIdx.x; i < Dx; i += blockDim.x) {
        float y = lns[i] * (buf[i] - mu) * inv + lnb[i];
        h[(size_t)tok * Dx + i] = rna_tf32(y);
    }
}

// ---------------- MMA primitives ----------------
__device__ __forceinline__ void ldsm_x4(uint32_t* r, uint32_t addr) {
    asm volatile("ldmatrix.sync.aligned.m8n8.x4.shared.b16 {%0,%1,%2,%3}, [%4];"
                 : "=r"(r[0]), "=r"(r[1]), "=r"(r[2]), "=r"(r[3]) : "r"(addr));
}
__device__ __forceinline__ void mma_tf32(float* c, const uint32_t* a, uint32_t b0, uint32_t b1) {
    asm volatile("mma.sync.aligned.m16n8k8.row.col.f32.tf32.tf32.f32 "
                 "{%0,%1,%2,%3}, {%4,%5,%6,%7}, {%8,%9}, {%0,%1,%2,%3};"
                 : "+f"(c[0]), "+f"(c[1]), "+f"(c[2]), "+f"(c[3])
                 : "r"(a[0]), "r"(a[1]), "r"(a[2]), "r"(a[3]), "r"(b0), "r"(b1));
}
__device__ __forceinline__ void cp16(void* dst, const void* src) {
    uint32_t d = (uint32_t)__cvta_generic_to_shared(dst);
    asm volatile("cp.async.cg.shared.global [%0], [%1], 16;" :: "r"(d), "l"(src));
}

// ---------------- TF32 dense GEMM ----------------
#define TF_STRIDE 36
#define TF_STAGE (128 * TF_STRIDE * 2)
#define TF_OFF_B (128 * TF_STRIDE)
#define TF_SMEM_BYTES (2 * TF_STAGE * 4)

__device__ __forceinline__ void tf_load_stage(
    float* sm, int s, int k0, int tid, int m0, int n0,
    const float* __restrict__ A, const float* __restrict__ Bt, int K)
{
    float* st = sm + s * TF_STAGE;
    #pragma unroll
    for (int i = 0; i < 4; i++) {
        int idx = tid + i * 256;
        int r = idx >> 3, c = (idx & 7) * 4;
        cp16(st + r * TF_STRIDE + c, A + (size_t)(m0 + r) * K + k0 + c);
        cp16(st + TF_OFF_B + r * TF_STRIDE + c, Bt + (size_t)(n0 + r) * K + k0 + c);
    }
    asm volatile("cp.async.commit_group;");
}

template<int MODE>
__device__ __forceinline__ void tf_gemm_body(
    const float* __restrict__ A, const float* __restrict__ Bt,
    const float* __restrict__ bias, float* __restrict__ C,
    int M, int N, int K, int bxb, int byb, float* sm)
{
    const int tid = threadIdx.x;
    const int lane = tid & 31;
    const int wid = tid >> 5;
    const int warp_m = wid & 3;
    const int warp_n = wid >> 2;
    const int m0 = byb * 128;
    const int n0 = bxb * 128;

    float acc[2][8][4];
    #pragma unroll
    for (int mt = 0; mt < 2; mt++) {
        #pragma unroll
        for (int nt = 0; nt < 8; nt++) {
            acc[mt][nt][0] = 0.f; acc[mt][nt][1] = 0.f;
            acc[mt][nt][2] = 0.f; acc[mt][nt][3] = 0.f;
        }
    }

    const int phase = lane >> 3;
    const int rli = lane & 7;
    const int a_roff = (phase & 1) * 8 + rli;
    const int a_koff = (phase >> 1) * 4;
    const int b_roff = (phase >> 1) * 8 + rli;
    const int b_koff = (phase & 1) * 4;

    const int nk = K >> 5;
    tf_load_stage(sm, 0, 0, tid, m0, n0, A, Bt, K);

    for (int kt = 0; kt < nk; kt++) {
        const int s = kt & 1;
        asm volatile("cp.async.wait_group 0;");
        __syncthreads();
        if (kt + 1 < nk)
            tf_load_stage(sm, s ^ 1, (kt + 1) * 32, tid, m0, n0, A, Bt, K);

        float* stA = sm + s * TF_STAGE;
        float* stB = stA + TF_OFF_B;

        #pragma unroll
        for (int kk = 0; kk < 32; kk += 8) {
            uint32_t aa0[4], aa1[4];
            ldsm_x4(aa0, (uint32_t)__cvta_generic_to_shared(
                stA + (warp_m * 32 + a_roff) * TF_STRIDE + kk + a_koff));
            ldsm_x4(aa1, (uint32_t)__cvta_generic_to_shared(
                stA + (warp_m * 32 + 16 + a_roff) * TF_STRIDE + kk + a_koff));
            #pragma unroll
            for (int p = 0; p < 4; p++) {
                uint32_t bb[4];
                ldsm_x4(bb, (uint32_t)__cvta_generic_to_shared(
                    stB + (warp_n * 64 + p * 16 + b_roff) * TF_STRIDE + kk + b_koff));
                int nt0 = p * 2;
                int nt1 = p * 2 + 1;
                mma_tf32(acc[0][nt0], aa0, bb[0], bb[1]);
                mma_tf32(acc[0][nt1], aa0, bb[2], bb[3]);
                mma_tf32(acc[1][nt0], aa1, bb[0], bb[1]);
                mma_tf32(acc[1][nt1], aa1, bb[2], bb[3]);
            }
        }
    }

    const int grp = lane >> 2;
    const int tig = lane & 3;
    #pragma unroll
    for (int mt = 0; mt < 2; mt++) {
        #pragma unroll
        for (int nt = 0; nt < 8; nt++) {
            int col = n0 + warp_n * 64 + nt * 8 + tig * 2;
            float b0 = bias[col];
            float b1 = bias[col + 1];
            #pragma unroll
            for (int half = 0; half < 2; half++) {
                int row = m0 + warp_m * 32 + mt * 16 + grp + half * 8;
                float v0 = acc[mt][nt][half * 2 + 0] + b0;
                float v1 = acc[mt][nt][half * 2 + 1] + b1;
                if (MODE == 3) {
                    v0 = 0.5f * v0 * (1.f + erff(v0 * 0.70710678118654752f));
                    v1 = 0.5f * v1 * (1.f + erff(v1 * 0.70710678118654752f));
                }
                if (MODE == 3 || MODE == 4) {
                    C[(size_t)row * N + col]     = rna_tf32(v0);
                    C[(size_t)row * N + col + 1] = rna_tf32(v1);
                } else {
                    C[(size_t)row * N + col]     = v0;
                    C[(size_t)row * N + col + 1] = v1;
                }
            }
        }
    }
}

template<int MODE>
__global__ void __launch_bounds__(256, 2) tf_gemm_kernel(
    const float* __restrict__ A, const float* __restrict__ Bt,
    const float* __restrict__ bias, float* __restrict__ C,
    int M, int N, int K)
{
    extern __shared__ __align__(16) float sm[];
    tf_gemm_body<MODE>(A, Bt, bias, C, M, N, K, blockIdx.x, blockIdx.y, sm);
}

__global__ void __launch_bounds__(256, 2) tf_qkv_kernel(
    const float* __restrict__ A, const float* __restrict__ Bt,
    const float* __restrict__ bq, const float* __restrict__ bk, const float* __restrict__ bv,
    float* __restrict__ q, float* __restrict__ k, float* __restrict__ v)
{
    extern __shared__ __align__(16) float sm[];
    int z = blockIdx.z;
    size_t woff = (size_t)z * nDD;
    const float* bias = (z == 0) ? bq : (z == 1) ? bk : bv;
    float* C = (z == 0) ? q : (z == 1) ? k : v;
    tf_gemm_body<4>(A, Bt + woff, bias, C, TOK, Dx, Dx, blockIdx.x, blockIdx.y, sm);
}

// ---------------- attention helpers ----------------
__device__ __forceinline__ int mid_block_idx(int n, int g, const int* __restrict__ randb) {
    if (g == 0) return 0;
    if (g == 1) return NBx - 1;
    if (g < 5)  return n - 3 + g;
    return randb[(n - 1) * Rx + (g - 5)];
}

#define FT_STRIDE 68
__device__ __forceinline__ void load_ftile(
    float (*dst)[FT_STRIDE], const float* __restrict__ src, int gstride, int tid)
{
    #pragma unroll
    for (int i = 0; i < 4; i++) {
        int idx = tid + i * 256;
        int r = idx >> 4, c = (idx & 15) * 4;
        *(float4*)&dst[r][c] = *(const float4*)(src + (size_t)r * gstride + c);
    }
}

// ---------------- fused middle-block attention (tf32, 64 q-rows / CTA) ----------
#define SROW 516
#define MID_SMEM (64 * SROW * 4 + 2 * 64 * FT_STRIDE * 4)

__global__ void __launch_bounds__(256, 1) mid_fused_kernel(
    const float* __restrict__ q, const float* __restrict__ k, const float* __restrict__ v,
    const int* __restrict__ randb, const int* __restrict__ amask,
    float* __restrict__ ctx)
{
    extern __shared__ __align__(16) char smraw[];
    float (*Sf)[SROW] = (float(*)[SROW])smraw;
    float (*Qs)[FT_STRIDE] = (float(*)[FT_STRIDE])(smraw + 64 * SROW * 4);
    float (*Ks)[FT_STRIDE] = (float(*)[FT_STRIDE])(smraw + 64 * SROW * 4 + 64 * FT_STRIDE * 4);

    int n = blockIdx.x + 1, h = blockIdx.y, b = blockIdx.z;
    int tid = threadIdx.x, lane = tid & 31, wid = tid >> 5;
    int warp_m = wid & 3, warp_n = wid >> 2;

    const int phase = lane >> 3;
    const int rli = lane & 7;
    const int a_roff = (phase & 1) * 8 + rli;
    const int a_koff = (phase >> 1) * 4;
    const int b_roff = (phase >> 1) * 8 + rli;
    const int b_koff = (phase & 1) * 4;

    size_t qoff = ((size_t)b * Sx + n * 64) * Dx + h * 64;
    load_ftile(Qs, q + qoff, Dx, tid);

    // --- phase 1: scores ---
    for (int g = 0; g < NGx; g++) {
        int kb = mid_block_idx(n, g, randb);
        size_t koff = ((size_t)b * Sx + kb * 64) * Dx + h * 64;
        __syncthreads();
        load_ftile(Ks, k + koff, Dx, tid);
        __syncthreads();

        float acc[4][4];
        #pragma unroll
        for (int j = 0; j < 4; j++) {
            acc[j][0] = 0.f; acc[j][1] = 0.f; acc[j][2] = 0.f; acc[j][3] = 0.f;
        }
        #pragma unroll
        for (int kk = 0; kk < 64; kk += 8) {
            uint32_t aa[4];
            ldsm_x4(aa, (uint32_t)__cvta_generic_to_shared(
                &Qs[warp_m * 16 + a_roff][kk + a_koff]));
            #pragma unroll
            for (int p = 0; p < 2; p++) {
                uint32_t bb[4];
                ldsm_x4(bb, (uint32_t)__cvta_generic_to_shared(
                    &Ks[warp_n * 32 + p * 16 + b_roff][kk + b_koff]));
                mma_tf32(acc[p * 2 + 0], aa, bb[0], bb[1]);
                mma_tf32(acc[p * 2 + 1], aa, bb[2], bb[3]);
            }
        }

        int r0 = warp_m * 16 + (lane >> 2);
        int mask_base = b * Sx + kb * 64;
        #pragma unroll
        for (int j = 0; j < 4; j++) {
            int ki = warp_n * 32 + j * 8 + (lane & 3) * 2;
            float m0 = (1.0f - (float)amask[mask_base + ki]) * -1e9f;
            float m1 = (1.0f - (float)amask[mask_base + ki + 1]) * -1e9f;
            Sf[r0][g * 64 + ki]           = acc[j][0] * 0.125f + m0;
            Sf[r0][g * 64 + ki + 1]       = acc[j][1] * 0.125f + m1;
            Sf[r0 + 8][g * 64 + ki]       = acc[j][2] * 0.125f + m0;
            Sf[r0 + 8][g * 64 + ki + 1]   = acc[j][3] * 0.125f + m1;
        }
    }
    __syncthreads();

    // --- phase 2: softmax ---
    for (int rr = 0; rr < 8; rr++) {
        int row = wid * 8 + rr;
        float vv[16];
        float m = -3.4e38f;
        #pragma unroll
        for (int j = 0; j < 16; j++) {
            vv[j] = Sf[row][lane + 32 * j];
            m = fmaxf(m, vv[j]);
        }
        #pragma unroll
        for (int o = 16; o; o >>= 1) m = fmaxf(m, __shfl_xor_sync(0xffffffffu, m, o));
        float s = 0.f;
        #pragma unroll
        for (int j = 0; j < 16; j++) { vv[j] = fexp(vv[j] - m); s += vv[j]; }
        #pragma unroll
        for (int o = 16; o; o >>= 1) s += __shfl_xor_sync(0xffffffffu, s, o);
        float inv = 1.f / s;
        #pragma unroll
        for (int j = 0; j < 16; j++) Sf[row][lane + 32 * j] = rna_tf32(vv[j] * inv);
    }
    __syncthreads();

    // --- phase 3: PV ---
    float acc[4][4];
    #pragma unroll
    for (int j = 0; j < 4; j++) {
        acc[j][0] = 0.f; acc[j][1] = 0.f; acc[j][2] = 0.f; acc[j][3] = 0.f;
    }
    const int ck = lane & 3;
    const int nr = lane >> 2;
    for (int g = 0; g < NGx; g++) {
        int kb = mid_block_idx(n, g, randb);
        size_t voff = ((size_t)b * Sx + kb * 64) * Dx + h * 64;
        __syncthreads();
        load_ftile(Ks, v + voff, Dx, tid);
        __syncthreads();
        #pragma unroll
        for (int kk = 0; kk < 64; kk += 8) {
            uint32_t aa[4];
            ldsm_x4(aa, (uint32_t)__cvta_generic_to_shared(
                &Sf[warp_m * 16 + a_roff][g * 64 + kk + a_koff]));
            #pragma unroll
            for (int j = 0; j < 4; j++) {
                int n0 = warp_n * 32 + j * 8 + nr;
                uint32_t b0 = __float_as_uint(Ks[kk + ck][n0]);
                uint32_t b1 = __float_as_uint(Ks[kk + 4 + ck][n0]);
                mma_tf32(acc[j], aa, b0, b1);
            }
        }
    }

    float* cbase = ctx + ((size_t)b * Sx + n * 64) * Dx + h * 64;
    int pr = warp_m * 16 + (lane >> 2);
    #pragma unroll
    for (int j = 0; j < 4; j++) {
        int col = warp_n * 32 + j * 8 + (lane & 3) * 2;
        cbase[(size_t)pr * Dx + col]           = rna_tf32(acc[j][0]);
        cbase[(size_t)pr * Dx + col + 1]       = rna_tf32(acc[j][1]);
        cbase[(size_t)(pr + 8) * Dx + col]     = rna_tf32(acc[j][2]);
        cbase[(size_t)(pr + 8) * Dx + col + 1] = rna_tf32(acc[j][3]);
    }
}

// ---------------- edge scores (tf32) ----------------
__device__ __forceinline__ void score_tile_tf(
    const float (*Qs)[FT_STRIDE], const float (*Ks)[FT_STRIDE],
    float acc[4][4], int lane, int warp_m, int warp_n)
{
    const int phase = lane >> 3;
    const int rli = lane & 7;
    const int a_roff = (phase & 1) * 8 + rli;
    const int a_koff = (phase >> 1) * 4;
    const int b_roff = (phase >> 1) * 8 + rli;
    const int b_koff = (phase & 1) * 4;

    #pragma unroll
    for (int kk = 0; kk < 64; kk += 8) {
        uint32_t aa[4];
        ldsm_x4(aa, (uint32_t)__cvta_generic_to_shared(
            &Qs[warp_m * 16 + a_roff][kk + a_koff]));
        #pragma unroll
        for (int p = 0; p < 2; p++) {
            uint32_t bb[4];
            ldsm_x4(bb, (uint32_t)__cvta_generic_to_shared(
                &Ks[warp_n * 32 + p * 16 + b_roff][kk + b_koff]));
            mma_tf32(acc[p * 2 + 0], aa, bb[0], bb[1]);
            mma_tf32(acc[p * 2 + 1], aa, bb[2], bb[3]);
        }
    }
}

__device__ __forceinline__ void pv_tile_tf(
    const float* __restrict__ P, int pstride, int pcol0,
    const float (*Vs)[FT_STRIDE],
    float acc[4][4], int lane, int warp_m, int warp_n)
{
    const int phase = lane >> 3;
    const int rli = lane & 7;
    const int a_roff = (phase & 1) * 8 + rli;
    const int a_koff = (phase >> 1) * 4;
    const int ck = lane & 3;
    const int nr = lane >> 2;

    #pragma unroll
    for (int kk = 0; kk < 64; kk += 8) {
        uint32_t aa[4];
        ldsm_x4(aa, (uint32_t)__cvta_generic_to_shared(
            P + (size_t)(warp_m * 16 + a_roff) * pstride + pcol0 + kk + a_koff));
        #pragma unroll
        for (int j = 0; j < 4; j++) {
            int n0 = warp_n * 32 + j * 8 + nr;
            uint32_t b0 = __float_as_uint(Vs[kk + ck][n0]);
            uint32_t b1 = __float_as_uint(Vs[kk + 4 + ck][n0]);
            mma_tf32(acc[j], aa, b0, b1);
        }
    }
}

__global__ void __launch_bounds__(256) edge_scores_tf(
    const float* __restrict__ q, const float* __restrict__ k,
    const int* __restrict__ amask, float* __restrict__ sedge)
{
    int kb = blockIdx.x, h = blockIdx.y;
    int e = blockIdx.z & 1, b = blockIdx.z >> 1;
    int qb = e ? (NBx - 1) : 0;
    __shared__ float Qs[64][FT_STRIDE];
    __shared__ float Ks[64][FT_STRIDE];
    int tid = threadIdx.x, lane = tid & 31, wid = tid >> 5;
    int warp_m = wid & 3, warp_n = wid >> 2;

    size_t qoff = ((size_t)b * Sx + qb * 64) * Dx + h * 64;
    size_t koff = ((size_t)b * Sx + kb * 64) * Dx + h * 64;
    load_ftile(Qs, q + qoff, Dx, tid);
    load_ftile(Ks, k + koff, Dx, tid);
    __syncthreads();

    float acc[4][4];
    #pragma unroll
    for (int j = 0; j < 4; j++) {
        acc[j][0] = 0.f; acc[j][1] = 0.f; acc[j][2] = 0.f; acc[j][3] = 0.f;
    }
    score_tile_tf(Qs, Ks, acc, lane, warp_m, warp_n);

    float* out = sedge + ((size_t)((b * NHx + h) * 2 + e)) * (64 * Sx);
    int r0 = warp_m * 16 + (lane >> 2);
    int mask_base = b * Sx + kb * 64;
    #pragma unroll
    for (int j = 0; j < 4; j++) {
        int ki = warp_n * 32 + j * 8 + (lane & 3) * 2;
        float m0 = (1.0f - (float)amask[mask_base + ki]) * -1e9f;
        float m1 = (1.0f - (float)amask[mask_base + ki + 1]) * -1e9f;
        out[(size_t)r0 * Sx + kb * 64 + ki]           = acc[j][0] * 0.125f + m0;
        out[(size_t)r0 * Sx + kb * 64 + ki + 1]       = acc[j][1] * 0.125f + m1;
        out[(size_t)(r0 + 8) * Sx + kb * 64 + ki]     = acc[j][2] * 0.125f + m0;
        out[(size_t)(r0 + 8) * Sx + kb * 64 + ki + 1] = acc[j][3] * 0.125f + m1;
    }
}

__global__ void softmax_rna_kernel(float* __restrict__ s, int L) {
    extern __shared__ float buf[];
    size_t base = (size_t)blockIdx.x * L;
    float m = -3.4e38f;
    for (int i = threadIdx.x; i < L; i += blockDim.x) {
        float x = s[base + i];
        buf[i] = x;
        m = fmaxf(m, x);
    }
    m = blk_max(m);
    float lsum = 0.f;
    for (int i = threadIdx.x; i < L; i += blockDim.x) {
        float e = fexp(buf[i] - m);
        buf[i] = e;
        lsum += e;
    }
    float sum = blk_sum(lsum);
    float inv = 1.f / sum;
    for (int i = threadIdx.x; i < L; i += blockDim.x)
        s[base + i] = rna_tf32(buf[i] * inv);
}

__global__ void __launch_bounds__(256) edge_pv_tf(
    const float* __restrict__ p, const float* __restrict__ v, float* __restrict__ ctx)
{
    int h = blockIdx.x;
    int e = blockIdx.y & 1, b = blockIdx.y >> 1;
    int chunk = blockIdx.z;
    int qb = e ? (NBx - 1) : 0;
    __shared__ float Ps[64][FT_STRIDE];
    __shared__ float Vs[64][FT_STRIDE];
    int tid = threadIdx.x, lane = tid & 31, wid = tid >> 5;
    int warp_m = wid & 3, warp_n = wid >> 2;

    const float* prow = p + ((size_t)((b * NHx + h) * 2 + e)) * (64 * Sx);

    float acc[4][4];
    #pragma unroll
    for (int j = 0; j < 4; j++) {
        acc[j][0] = 0.f; acc[j][1] = 0.f; acc[j][2] = 0.f; acc[j][3] = 0.f;
    }

    for (int c8 = 0; c8 < 8; c8++) {
        int kb = chunk * 8 + c8;
        size_t voff = ((size_t)b * Sx + kb * 64) * Dx + h * 64;
        __syncthreads();
        load_ftile(Ps, prow + kb * 64, Sx, tid);
        load_ftile(Vs, v + voff, Dx, tid);
        __syncthreads();
        pv_tile_tf(&Ps[0][0], FT_STRIDE, 0, Vs, acc, lane, warp_m, warp_n);
    }

    float* cbase = ctx + ((size_t)b * Sx + qb * 64) * Dx + h * 64;
    int r0 = warp_m * 16 + (lane >> 2);
    #pragma unroll
    for (int j = 0; j < 4; j++) {
        int col = warp_n * 32 + j * 8 + (lane & 3) * 2;
        atomicAdd(&cbase[(size_t)r0 * Dx + col],           acc[j][0]);
        atomicAdd(&cbase[(size_t)r0 * Dx + col + 1],       acc[j][1]);
        atomicAdd(&cbase[(size_t)(r0 + 8) * Dx + col],     acc[j][2]);
        atomicAdd(&cbase[(size_t)(r0 + 8) * Dx + col + 1], acc[j][3]);
    }
}

__global__ void zero_edge_ctx(float* __restrict__ ctx) {
    int i = blockIdx.x * 256 + threadIdx.x;
    if (i >= Bx * 2 * 64 * Dx) return;
    int col = i % Dx;
    int t = i / Dx;
    int row = t % 64;  t /= 64;
    int e = t & 1;
    int b = t >> 1;
    int blk = e ? (NBx - 1) : 0;
    ctx[((size_t)b * Sx + blk * 64 + row) * Dx + col] = 0.f;
}

// ---------------- pooler ----------------
__global__ void pooler_kernel(const float* __restrict__ h, const float* __restrict__ pw,
                              const float* __restrict__ pb, float* __restrict__ out) {
    int j = blockIdx.x * blockDim.x + threadIdx.x;
    int b = blockIdx.y;
    if (j >= Dx) return;
    const float* hr = h + (size_t)b * Sx * Dx;
    float acc = pb[j];
    for (int kI = 0; kI < Dx; kI++) acc += hr[kI] * pw[(size_t)kI * Dx + j];
    out[b * Dx + j] = tanhf(acc);
}

// ---------------- host launcher ----------------
extern "C" void kernel_launch(void* const* d_in, const int* in_sizes, int n_in,
                              void* d_out, int out_size) {
    const int*   input_ids = (const int*)d_in[0];
    const int*   attn_mask = (const int*)d_in[1];
    const int*   tok_type  = (const int*)d_in[2];
    const int*   rand_blk  = (const int*)d_in[3];
    const float* word_emb  = (const float*)d_in[4];
    const float* type_emb  = (const float*)d_in[5];
    const float* pos_emb   = (const float*)d_in[6];
    const float* emb_ln_s  = (const float*)d_in[7];
    const float* emb_ln_b  = (const float*)d_in[8];
    const float* Wq = (const float*)d_in[9];  const float* bq = (const float*)d_in[10];
    const float* Wk = (const float*)d_in[11]; const float* bk = (const float*)d_in[12];
    const float* Wv = (const float*)d_in[13]; const float* bv = (const float*)d_in[14];
    const float* Wo = (const float*)d_in[15]; const float* bo = (const float*)d_in[16];
    const float* ln1_s = (const float*)d_in[17]; const float* ln1_b = (const float*)d_in[18];
    const float* W1 = (const float*)d_in[19]; const float* b1 = (const float*)d_in[20];
    const float* W2 = (const float*)d_in[21]; const float* b2 = (const float*)d_in[22];
    const float* ln2_s = (const float*)d_in[23]; const float* ln2_b = (const float*)d_in[24];
    const float* pool_w = (const float*)d_in[25]; const float* pool_b = (const float*)d_in[26];
    float* out = (float*)d_out;

    float *p_h = 0, *p_res = 0, *p_ctx = 0, *p_ff = 0, *p_wt = 0, *p_sedge = 0;
    float *p_q = 0, *p_k = 0, *p_v = 0;
    cudaGetSymbolAddress((void**)&p_h,     g_h);
    cudaGetSymbolAddress((void**)&p_res,   g_res);
    cudaGetSymbolAddress((void**)&p_ctx,   g_ctx);
    cudaGetSymbolAddress((void**)&p_ff,    g_ff);
    cudaGetSymbolAddress((void**)&p_wt,    g_wt);
    cudaGetSymbolAddress((void**)&p_sedge, g_sedge);
    cudaGetSymbolAddress((void**)&p_q,     g_q);
    cudaGetSymbolAddress((void**)&p_k,     g_k);
    cudaGetSymbolAddress((void**)&p_v,     g_v);

    static bool init_done = false;
    static cudaStream_t s2;
    static cudaEvent_t evF0, evT, evF[2], evJ[2];
    if (!init_done) {
        cudaFuncSetAttribute(tf_gemm_kernel<0>, cudaFuncAttributeMaxDynamicSharedMemorySize, TF_SMEM_BYTES);
        cudaFuncSetAttribute(tf_gemm_kernel<3>, cudaFuncAttributeMaxDynamicSharedMemorySize, TF_SMEM_BYTES);
        cudaFuncSetAttribute(tf_qkv_kernel, cudaFuncAttributeMaxDynamicSharedMemorySize, TF_SMEM_BYTES);
        cudaFuncSetAttribute(mid_fused_kernel, cudaFuncAttributeMaxDynamicSharedMemorySize, MID_SMEM);
        cudaStreamCreateWithFlags(&s2, cudaStreamNonBlocking);
        cudaEventCreateWithFlags(&evF0, cudaEventDisableTiming);
        cudaEventCreateWithFlags(&evT,  cudaEventDisableTiming);
        cudaEventCreateWithFlags(&evF[0], cudaEventDisableTiming);
        cudaEventCreateWithFlags(&evF[1], cudaEventDisableTiming);
        cudaEventCreateWithFlags(&evJ[0], cudaEventDisableTiming);
        cudaEventCreateWithFlags(&evJ[1], cudaEventDisableTiming);
        init_done = true;
    }

    const int M = TOK;
    // weight plane layout in g_wt:
    //   qkv[l]: l*3*nDD (+0/q, +nDD/k, +2nDD/v)   (l in 0..1)
    //   wo[l]:  6*nDD + l*nDD
    //   w1[l]:  8*nDD + l*nDF
    //   w2[l]:  8*nDD + 2*nDF + l*nDF
    float* wt_qkv0 = p_wt;
    float* wt_wo   = p_wt + (size_t)6 * nDD;
    float* wt_w1   = p_wt + (size_t)8 * nDD;
    float* wt_w2   = p_wt + (size_t)8 * nDD + (size_t)2 * nDF;

    // fork: weight transposes on s2, overlapped with embed_ln on stream 0
    cudaEventRecord(evF0, 0);
    cudaStreamWaitEvent(s2, evF0, 0);
    trans_round_kernel<<<dim3(Dx/32, Dx/32, 2), dim3(32, 8), 0, s2>>>(Wq, wt_qkv0,           Dx, Dx, nDD, (size_t)3*nDD);
    trans_round_kernel<<<dim3(Dx/32, Dx/32, 2), dim3(32, 8), 0, s2>>>(Wk, wt_qkv0 + nDD,     Dx, Dx, nDD, (size_t)3*nDD);
    trans_round_kernel<<<dim3(Dx/32, Dx/32, 2), dim3(32, 8), 0, s2>>>(Wv, wt_qkv0 + 2*nDD,   Dx, Dx, nDD, (size_t)3*nDD);
    trans_round_kernel<<<dim3(Dx/32, Dx/32, 2), dim3(32, 8), 0, s2>>>(Wo, wt_wo,             Dx, Dx, nDD, (size_t)nDD);
    trans_round_kernel<<<dim3(FFx/32, Dx/32, 2), dim3(32, 8), 0, s2>>>(W1, wt_w1,            Dx, FFx, nDF, (size_t)nDF);
    trans_round_kernel<<<dim3(Dx/32, FFx/32, 2), dim3(32, 8), 0, s2>>>(W2, wt_w2,            FFx, Dx, nDF, (size_t)nDF);
    cudaEventRecord(evT, s2);

    embed_ln_kernel<<<TOK, 256>>>(input_ids, tok_type, word_emb, type_emb, pos_emb,
                                  emb_ln_s, emb_ln_b);
    cudaStreamWaitEvent(0, evT, 0);

    for (int l = 0; l < 2; l++) {
        const float* bql = bq + (size_t)l * Dx;
        const float* bkl = bk + (size_t)l * Dx;
        const float* bvl = bv + (size_t)l * Dx;
        const float* bol = bo + (size_t)l * Dx;
        const float* b1l = b1 + (size_t)l * FFx;
        const float* b2l = b2 + (size_t)l * Dx;
        const float* l1s = ln1_s + (size_t)l * Dx; const float* l1b = ln1_b + (size_t)l * Dx;
        const float* l2s = ln2_s + (size_t)l * Dx; const float* l2b = ln2_b + (size_t)l * Dx;

        // QKV (tf32) on stream 0
        tf_qkv_kernel<<<dim3(Dx / 128, M / 128, 3), 256, TF_SMEM_BYTES>>>(
            p_h, wt_qkv0 + (size_t)l * 3 * nDD, bql, bkl, bvl, p_q, p_k, p_v);

        // fork edge path onto s2 (reads q/k/v, writes edge ctx rows)
        cudaEventRecord(evF[l], 0);
        cudaStreamWaitEvent(s2, evF[l], 0);
        edge_scores_tf<<<dim3(NBx, NHx, Bx * 2), 256, 0, s2>>>(p_q, p_k, attn_mask, p_sedge);
        softmax_rna_kernel<<<Bx * NHx * 2 * BSx, 256, Sx * sizeof(float), s2>>>(p_sedge, Sx);
        zero_edge_ctx<<<(Bx * 2 * 64 * Dx + 255) / 256, 256, 0, s2>>>(p_ctx);
        edge_pv_tf<<<dim3(NHx, Bx * 2, 8), 256, 0, s2>>>(p_sedge, p_v, p_ctx);
        cudaEventRecord(evJ[l], s2);

        // mid path on stream 0 (writes mid ctx rows)
        mid_fused_kernel<<<dim3(NMID, NHx, Bx), 256, MID_SMEM>>>(
            p_q, p_k, p_v, rand_blk, attn_mask, p_ctx);

        // join before O-projection (reads full ctx)
        cudaStreamWaitEvent(0, evJ[l], 0);

        tf_gemm_kernel<0><<<dim3(Dx / 128, M / 128), 256, TF_SMEM_BYTES>>>(
            p_ctx, wt_wo + (size_t)l * nDD, bol, p_res, M, Dx, Dx);
        add_ln_kernel<<<TOK, 256>>>(p_h, p_res, l1s, l1b);

        // FFN (tf32)
        tf_gemm_kernel<3><<<dim3(FFx / 128, M / 128), 256, TF_SMEM_BYTES>>>(
            p_h, wt_w1 + (size_t)l * nDF, b1l, p_ff, M, FFx, Dx);
        tf_gemm_kernel<0><<<dim3(Dx / 128, M / 128), 256, TF_SMEM_BYTES>>>(
            p_ff, wt_w2 + (size_t)l * nDF, b2l, p_res, M, Dx, FFx);
        add_ln_kernel<<<TOK, 256>>>(p_h, p_res, l2s, l2b);
    }

    pooler_kernel<<<dim3((Dx + 127) / 128, Bx), 128>>>(p_h, pool_w, pool_b, out);
}

// round 17
// speedup vs baseline: 1.0294x; 1.0227x over previous
#include <cuda_runtime.h>
#include <cuda_bf16.h>
#include <cstdint>
#include <math.h>

#define Bx 2
#define Sx 4096
#define Dx 768
#define NHx 12
#define HDx 64
#define BSx 64
#define NBx 64
#define FFx 3072
#define Rx 3
#define NGx 8
#define NMID 62
#define TOK (Bx*Sx)
#define nDD (Dx*Dx)
#define nDF (Dx*FFx)

// ---------------- scratch ----------------
__device__ float g_h[(size_t)TOK*Dx];
__device__ float g_res[(size_t)TOK*Dx];
__device__ float g_ctx[(size_t)TOK*Dx];
__device__ float g_ff[(size_t)TOK*FFx];
__device__ float g_wt[(size_t)8*nDD + (size_t)4*nDF];
__device__ float g_q[(size_t)TOK*Dx];
__device__ float g_k[(size_t)TOK*Dx];
__device__ float g_v[(size_t)TOK*Dx];
__device__ float g_sedge[(size_t)Bx*NHx*2*BSx*Sx];

// ---------------- helpers ----------------
__device__ __forceinline__ float rna_tf32(float x) {
    uint32_t o;
    asm("cvt.rna.tf32.f32 %0, %1;" : "=r"(o) : "f"(x));
    return __uint_as_float(o);
}
__device__ __forceinline__ float fexp(float x) {
    x = fmaxf(x, -80.f);
    float t = fmaf(x, 1.4426950408889634f, 12582912.0f);
    float i = t - 12582912.0f;
    float f = fmaf(x, 1.4426950408889634f, -i);
    float pr = 1.5403530e-4f;
    pr = fmaf(pr, f, 1.3333558e-3f);
    pr = fmaf(pr, f, 9.6181291e-3f);
    pr = fmaf(pr, f, 5.5504109e-2f);
    pr = fmaf(pr, f, 2.4022651e-1f);
    pr = fmaf(pr, f, 6.9314718e-1f);
    pr = fmaf(pr, f, 1.0f);
    int ii = (int)i;
    float sc = __int_as_float((ii + 127) << 23);
    return pr * sc;
}

__device__ __forceinline__ float blk_sum(float v) {
    __shared__ float red[33];
    #pragma unroll
    for (int o = 16; o; o >>= 1) v += __shfl_down_sync(0xffffffffu, v, o);
    int lane = threadIdx.x & 31, w = threadIdx.x >> 5;
    __syncthreads();
    if (lane == 0) red[w] = v;
    __syncthreads();
    if (w == 0) {
        float x = (lane < ((blockDim.x + 31) >> 5)) ? red[lane] : 0.f;
        #pragma unroll
        for (int o = 16; o; o >>= 1) x += __shfl_down_sync(0xffffffffu, x, o);
        if (lane == 0) red[32] = x;
    }
    __syncthreads();
    return red[32];
}

__device__ __forceinline__ float blk_max(float v) {
    __shared__ float redm[33];
    #pragma unroll
    for (int o = 16; o; o >>= 1) v = fmaxf(v, __shfl_down_sync(0xffffffffu, v, o));
    int lane = threadIdx.x & 31, w = threadIdx.x >> 5;
    __syncthreads();
    if (lane == 0) redm[w] = v;
    __syncthreads();
    if (w == 0) {
        float x = (lane < ((blockDim.x + 31) >> 5)) ? redm[lane] : -3.4e38f;
        #pragma unroll
        for (int o = 16; o; o >>= 1) x = fmaxf(x, __shfl_xor_sync(0xffffffffu, x, o));
        if (lane == 0) redm[32] = x;
    }
    __syncthreads();
    return redm[32];
}

// ---------------- weight transpose + tf32 round (z-batched over layers) ----------
__global__ void trans_round_kernel(const float* __restrict__ in, float* __restrict__ out,
                                   int K, int N, size_t zin, size_t zout) {
    __shared__ float t[32][33];
    in  += (size_t)blockIdx.z * zin;
    out += (size_t)blockIdx.z * zout;
    int n0 = blockIdx.x * 32, k0 = blockIdx.y * 32;
    int tx = threadIdx.x, ty = threadIdx.y;
    #pragma unroll
    for (int i = ty; i < 32; i += 8) t[i][tx] = in[(size_t)(k0 + i) * N + n0 + tx];
    __syncthreads();
    #pragma unroll
    for (int i = ty; i < 32; i += 8)
        out[(size_t)(n0 + i) * K + k0 + tx] = rna_tf32(t[tx][i]);
}

// ---------------- embeddings + LN ----------------
__global__ void embed_ln_kernel(const int* __restrict__ ids, const int* __restrict__ tt,
                                const float* __restrict__ wemb, const float* __restrict__ temb,
                                const float* __restrict__ pemb,
                                const float* __restrict__ lns, const float* __restrict__ lnb) {
    int tok = blockIdx.x;
    int pos = tok % Sx;
    const float* w = wemb + (size_t)ids[tok] * Dx;
    const float* t = temb + (size_t)tt[tok] * Dx;
    const float* p = pemb + (size_t)pos * Dx;
    __shared__ float buf[Dx];
    float ls = 0.f, lq = 0.f;
    for (int i = threadIdx.x; i < Dx; i += blockDim.x) {
        float x = w[i] + t[i] + p[i];
        buf[i] = x; ls += x; lq += x * x;
    }
    float sum = blk_sum(ls);
    float sq  = blk_sum(lq);
    float mu = sum * (1.f / Dx);
    float var = sq * (1.f / Dx) - mu * mu;
    float inv = rsqrtf(var + 1e-12f);
    for (int i = threadIdx.x; i < Dx; i += blockDim.x) {
        float y = lns[i] * (buf[i] - mu) * inv + lnb[i];
        g_h[(size_t)tok * Dx + i] = rna_tf32(y);
    }
}

__global__ void add_ln_kernel(float* __restrict__ h, const float* __restrict__ r,
                              const float* __restrict__ lns, const float* __restrict__ lnb) {
    int tok = blockIdx.x;
    __shared__ float buf[Dx];
    float ls = 0.f, lq = 0.f;
    for (int i = threadIdx.x; i < Dx; i += blockDim.x) {
        float x = h[(size_t)tok * Dx + i] + r[(size_t)tok * Dx + i];
        buf[i] = x; ls += x; lq += x * x;
    }
    float sum = blk_sum(ls);
    float sq  = blk_sum(lq);
    float mu = sum * (1.f / Dx);
    float var = sq * (1.f / Dx) - mu * mu;
    float inv = rsqrtf(var + 1e-12f);
    for (int i = threadIdx.x; i < Dx; i += blockDim.x) {
        float y = lns[i] * (buf[i] - mu) * inv + lnb[i];
        h[(size_t)tok * Dx + i] = rna_tf32(y);
    }
}

// ---------------- MMA primitives ----------------
__device__ __forceinline__ void ldsm_x4(uint32_t* r, uint32_t addr) {
    asm volatile("ldmatrix.sync.aligned.m8n8.x4.shared.b16 {%0,%1,%2,%3}, [%4];"
                 : "=r"(r[0]), "=r"(r[1]), "=r"(r[2]), "=r"(r[3]) : "r"(addr));
}
__device__ __forceinline__ void mma_tf32(float* c, const uint32_t* a, uint32_t b0, uint32_t b1) {
    asm volatile("mma.sync.aligned.m16n8k8.row.col.f32.tf32.tf32.f32 "
                 "{%0,%1,%2,%3}, {%4,%5,%6,%7}, {%8,%9}, {%0,%1,%2,%3};"
                 : "+f"(c[0]), "+f"(c[1]), "+f"(c[2]), "+f"(c[3])
                 : "r"(a[0]), "r"(a[1]), "r"(a[2]), "r"(a[3]), "r"(b0), "r"(b1));
}
__device__ __forceinline__ void cp16(void* dst, const void* src) {
    uint32_t d = (uint32_t)__cvta_generic_to_shared(dst);
    asm volatile("cp.async.cg.shared.global [%0], [%1], 16;" :: "r"(d), "l"(src));
}

// ---------------- TF32 dense GEMM ----------------
#define TF_STRIDE 36
#define TF_STAGE (128 * TF_STRIDE * 2)
#define TF_OFF_B (128 * TF_STRIDE)
#define TF_SMEM_BYTES (2 * TF_STAGE * 4)

__device__ __forceinline__ void tf_load_stage(
    float* sm, int s, int k0, int tid, int m0, int n0,
    const float* __restrict__ A, const float* __restrict__ Bt, int K)
{
    float* st = sm + s * TF_STAGE;
    #pragma unroll
    for (int i = 0; i < 4; i++) {
        int idx = tid + i * 256;
        int r = idx >> 3, c = (idx & 7) * 4;
        cp16(st + r * TF_STRIDE + c, A + (size_t)(m0 + r) * K + k0 + c);
        cp16(st + TF_OFF_B + r * TF_STRIDE + c, Bt + (size_t)(n0 + r) * K + k0 + c);
    }
    asm volatile("cp.async.commit_group;");
}

template<int MODE>
__device__ __forceinline__ void tf_gemm_body(
    const float* __restrict__ A, const float* __restrict__ Bt,
    const float* __restrict__ bias, float* __restrict__ C,
    int M, int N, int K, int bxb, int byb, float* sm)
{
    const int tid = threadIdx.x;
    const int lane = tid & 31;
    const int wid = tid >> 5;
    const int warp_m = wid & 3;
    const int warp_n = wid >> 2;
    const int m0 = byb * 128;
    const int n0 = bxb * 128;

    float acc[2][8][4];
    #pragma unroll
    for (int mt = 0; mt < 2; mt++) {
        #pragma unroll
        for (int nt = 0; nt < 8; nt++) {
            acc[mt][nt][0] = 0.f; acc[mt][nt][1] = 0.f;
            acc[mt][nt][2] = 0.f; acc[mt][nt][3] = 0.f;
        }
    }

    const int phase = lane >> 3;
    const int rli = lane & 7;
    const int a_roff = (phase & 1) * 8 + rli;
    const int a_koff = (phase >> 1) * 4;
    const int b_roff = (phase >> 1) * 8 + rli;
    const int b_koff = (phase & 1) * 4;

    const int nk = K >> 5;
    tf_load_stage(sm, 0, 0, tid, m0, n0, A, Bt, K);

    for (int kt = 0; kt < nk; kt++) {
        const int s = kt & 1;
        asm volatile("cp.async.wait_group 0;");
        __syncthreads();
        if (kt + 1 < nk)
            tf_load_stage(sm, s ^ 1, (kt + 1) * 32, tid, m0, n0, A, Bt, K);

        float* stA = sm + s * TF_STAGE;
        float* stB = stA + TF_OFF_B;

        #pragma unroll
        for (int kk = 0; kk < 32; kk += 8) {
            uint32_t aa0[4], aa1[4];
            ldsm_x4(aa0, (uint32_t)__cvta_generic_to_shared(
                stA + (warp_m * 32 + a_roff) * TF_STRIDE + kk + a_koff));
            ldsm_x4(aa1, (uint32_t)__cvta_generic_to_shared(
                stA + (warp_m * 32 + 16 + a_roff) * TF_STRIDE + kk + a_koff));
            #pragma unroll
            for (int p = 0; p < 4; p++) {
                uint32_t bb[4];
                ldsm_x4(bb, (uint32_t)__cvta_generic_to_shared(
                    stB + (warp_n * 64 + p * 16 + b_roff) * TF_STRIDE + kk + b_koff));
                int nt0 = p * 2;
                int nt1 = p * 2 + 1;
                mma_tf32(acc[0][nt0], aa0, bb[0], bb[1]);
                mma_tf32(acc[0][nt1], aa0, bb[2], bb[3]);
                mma_tf32(acc[1][nt0], aa1, bb[0], bb[1]);
                mma_tf32(acc[1][nt1], aa1, bb[2], bb[3]);
            }
        }
    }

    const int grp = lane >> 2;
    const int tig = lane & 3;
    #pragma unroll
    for (int mt = 0; mt < 2; mt++) {
        #pragma unroll
        for (int nt = 0; nt < 8; nt++) {
            int col = n0 + warp_n * 64 + nt * 8 + tig * 2;
            float b0 = bias[col];
            float b1 = bias[col + 1];
            #pragma unroll
            for (int half = 0; half < 2; half++) {
                int row = m0 + warp_m * 32 + mt * 16 + grp + half * 8;
                float v0 = acc[mt][nt][half * 2 + 0] + b0;
                float v1 = acc[mt][nt][half * 2 + 1] + b1;
                if (MODE == 3) {
                    v0 = 0.5f * v0 * (1.f + erff(v0 * 0.70710678118654752f));
                    v1 = 0.5f * v1 * (1.f + erff(v1 * 0.70710678118654752f));
                }
                if (MODE == 3 || MODE == 4) {
                    C[(size_t)row * N + col]     = rna_tf32(v0);
                    C[(size_t)row * N + col + 1] = rna_tf32(v1);
                } else {
                    C[(size_t)row * N + col]     = v0;
                    C[(size_t)row * N + col + 1] = v1;
                }
            }
        }
    }
}

template<int MODE>
__global__ void __launch_bounds__(256, 2) tf_gemm_kernel(
    const float* __restrict__ A, const float* __restrict__ Bt,
    const float* __restrict__ bias, float* __restrict__ C,
    int M, int N, int K)
{
    extern __shared__ __align__(16) float sm[];
    tf_gemm_body<MODE>(A, Bt, bias, C, M, N, K, blockIdx.x, blockIdx.y, sm);
}

__global__ void __launch_bounds__(256, 2) tf_qkv_kernel(
    const float* __restrict__ A, const float* __restrict__ Bt,
    const float* __restrict__ bq, const float* __restrict__ bk, const float* __restrict__ bv,
    float* __restrict__ q, float* __restrict__ k, float* __restrict__ v)
{
    extern __shared__ __align__(16) float sm[];
    int z = blockIdx.z;
    size_t woff = (size_t)z * nDD;
    const float* bias = (z == 0) ? bq : (z == 1) ? bk : bv;
    float* C = (z == 0) ? q : (z == 1) ? k : v;
    tf_gemm_body<4>(A, Bt + woff, bias, C, TOK, Dx, Dx, blockIdx.x, blockIdx.y, sm);
}

// ---------------- attention helpers ----------------
__device__ __forceinline__ int mid_block_idx(int n, int g, const int* __restrict__ randb) {
    if (g == 0) return 0;
    if (g == 1) return NBx - 1;
    if (g < 5)  return n - 3 + g;
    return randb[(n - 1) * Rx + (g - 5)];
}

#define FT_STRIDE 68
__device__ __forceinline__ void load_ftile(
    float (*dst)[FT_STRIDE], const float* __restrict__ src, int gstride, int tid)
{
    #pragma unroll
    for (int i = 0; i < 4; i++) {
        int idx = tid + i * 256;
        int r = idx >> 4, c = (idx & 15) * 4;
        *(float4*)&dst[r][c] = *(const float4*)(src + (size_t)r * gstride + c);
    }
}
// async version (cp.async, one commit group)
__device__ __forceinline__ void cp_ftile(
    float (*dst)[FT_STRIDE], const float* __restrict__ src, int gstride, int tid)
{
    #pragma unroll
    for (int i = 0; i < 4; i++) {
        int idx = tid + i * 256;
        int r = idx >> 4, c = (idx & 15) * 4;
        cp16(&dst[r][c], src + (size_t)r * gstride + c);
    }
    asm volatile("cp.async.commit_group;");
}

// ---------------- fused middle-block attention (tf32, async-pipelined K/V) ------
#define SROW 516
#define MID_SMEM (64 * SROW * 4 + 64 * FT_STRIDE * 4 + 2 * 64 * FT_STRIDE * 4)

__global__ void __launch_bounds__(256, 1) mid_fused_kernel(
    const float* __restrict__ q, const float* __restrict__ k, const float* __restrict__ v,
    const int* __restrict__ randb, const int* __restrict__ amask,
    float* __restrict__ ctx)
{
    extern __shared__ __align__(16) char smraw[];
    float (*Sf)[SROW] = (float(*)[SROW])smraw;
    float (*Qs)[FT_STRIDE] = (float(*)[FT_STRIDE])(smraw + 64 * SROW * 4);
    float (*K0)[FT_STRIDE] = (float(*)[FT_STRIDE])(smraw + 64 * SROW * 4 + 64 * FT_STRIDE * 4);
    float (*K1)[FT_STRIDE] = (float(*)[FT_STRIDE])(smraw + 64 * SROW * 4 + 2 * 64 * FT_STRIDE * 4);

    int n = blockIdx.x + 1, h = blockIdx.y, b = blockIdx.z;
    int tid = threadIdx.x, lane = tid & 31, wid = tid >> 5;
    int warp_m = wid & 3, warp_n = wid >> 2;

    const int phase = lane >> 3;
    const int rli = lane & 7;
    const int a_roff = (phase & 1) * 8 + rli;
    const int a_koff = (phase >> 1) * 4;
    const int b_roff = (phase >> 1) * 8 + rli;
    const int b_koff = (phase & 1) * 4;

    size_t qoff = ((size_t)b * Sx + n * 64) * Dx + h * 64;
    load_ftile(Qs, q + qoff, Dx, tid);

    // --- phase 1: scores (double-buffered async K) ---
    {
        int kb0 = mid_block_idx(n, 0, randb);
        cp_ftile(K0, k + ((size_t)b * Sx + kb0 * 64) * Dx + h * 64, Dx, tid);
    }
    for (int g = 0; g < NGx; g++) {
        float (*Ks)[FT_STRIDE] = (g & 1) ? K1 : K0;
        float (*Kn)[FT_STRIDE] = (g & 1) ? K0 : K1;
        asm volatile("cp.async.wait_group 0;");
        __syncthreads();
        if (g + 1 < NGx) {
            int kbn = mid_block_idx(n, g + 1, randb);
            cp_ftile(Kn, k + ((size_t)b * Sx + kbn * 64) * Dx + h * 64, Dx, tid);
        }

        float acc[4][4];
        #pragma unroll
        for (int j = 0; j < 4; j++) {
            acc[j][0] = 0.f; acc[j][1] = 0.f; acc[j][2] = 0.f; acc[j][3] = 0.f;
        }
        #pragma unroll
        for (int kk = 0; kk < 64; kk += 8) {
            uint32_t aa[4];
            ldsm_x4(aa, (uint32_t)__cvta_generic_to_shared(
                &Qs[warp_m * 16 + a_roff][kk + a_koff]));
            #pragma unroll
            for (int p = 0; p < 2; p++) {
                uint32_t bb[4];
                ldsm_x4(bb, (uint32_t)__cvta_generic_to_shared(
                    &Ks[warp_n * 32 + p * 16 + b_roff][kk + b_koff]));
                mma_tf32(acc[p * 2 + 0], aa, bb[0], bb[1]);
                mma_tf32(acc[p * 2 + 1], aa, bb[2], bb[3]);
            }
        }

        int kb = mid_block_idx(n, g, randb);
        int r0 = warp_m * 16 + (lane >> 2);
        int mask_base = b * Sx + kb * 64;
        #pragma unroll
        for (int j = 0; j < 4; j++) {
            int ki = warp_n * 32 + j * 8 + (lane & 3) * 2;
            float m0 = (1.0f - (float)amask[mask_base + ki]) * -1e9f;
            float m1 = (1.0f - (float)amask[mask_base + ki + 1]) * -1e9f;
            Sf[r0][g * 64 + ki]           = acc[j][0] * 0.125f + m0;
            Sf[r0][g * 64 + ki + 1]       = acc[j][1] * 0.125f + m1;
            Sf[r0 + 8][g * 64 + ki]       = acc[j][2] * 0.125f + m0;
            Sf[r0 + 8][g * 64 + ki + 1]   = acc[j][3] * 0.125f + m1;
        }
    }
    __syncthreads();

    // --- phase 2: softmax ---
    for (int rr = 0; rr < 8; rr++) {
        int row = wid * 8 + rr;
        float vv[16];
        float m = -3.4e38f;
        #pragma unroll
        for (int j = 0; j < 16; j++) {
            vv[j] = Sf[row][lane + 32 * j];
            m = fmaxf(m, vv[j]);
        }
        #pragma unroll
        for (int o = 16; o; o >>= 1) m = fmaxf(m, __shfl_xor_sync(0xffffffffu, m, o));
        float s = 0.f;
        #pragma unroll
        for (int j = 0; j < 16; j++) { vv[j] = fexp(vv[j] - m); s += vv[j]; }
        #pragma unroll
        for (int o = 16; o; o >>= 1) s += __shfl_xor_sync(0xffffffffu, s, o);
        float inv = 1.f / s;
        #pragma unroll
        for (int j = 0; j < 16; j++) Sf[row][lane + 32 * j] = rna_tf32(vv[j] * inv);
    }
    __syncthreads();

    // --- phase 3: PV (double-buffered async V) ---
    float acc[4][4];
    #pragma unroll
    for (int j = 0; j < 4; j++) {
        acc[j][0] = 0.f; acc[j][1] = 0.f; acc[j][2] = 0.f; acc[j][3] = 0.f;
    }
    const int ck = lane & 3;
    const int nr = lane >> 2;
    {
        int kb0 = mid_block_idx(n, 0, randb);
        cp_ftile(K0, v + ((size_t)b * Sx + kb0 * 64) * Dx + h * 64, Dx, tid);
    }
    for (int g = 0; g < NGx; g++) {
        float (*Vs)[FT_STRIDE] = (g & 1) ? K1 : K0;
        float (*Vn)[FT_STRIDE] = (g & 1) ? K0 : K1;
        asm volatile("cp.async.wait_group 0;");
        __syncthreads();
        if (g + 1 < NGx) {
            int kbn = mid_block_idx(n, g + 1, randb);
            cp_ftile(Vn, v + ((size_t)b * Sx + kbn * 64) * Dx + h * 64, Dx, tid);
        }
        #pragma unroll
        for (int kk = 0; kk < 64; kk += 8) {
            uint32_t aa[4];
            ldsm_x4(aa, (uint32_t)__cvta_generic_to_shared(
                &Sf[warp_m * 16 + a_roff][g * 64 + kk + a_koff]));
            #pragma unroll
            for (int j = 0; j < 4; j++) {
                int n0 = warp_n * 32 + j * 8 + nr;
                uint32_t b0 = __float_as_uint(Vs[kk + ck][n0]);
                uint32_t b1 = __float_as_uint(Vs[kk + 4 + ck][n0]);
                mma_tf32(acc[j], aa, b0, b1);
            }
        }
    }

    float* cbase = ctx + ((size_t)b * Sx + n * 64) * Dx + h * 64;
    int pr = warp_m * 16 + (lane >> 2);
    #pragma unroll
    for (int j = 0; j < 4; j++) {
        int col = warp_n * 32 + j * 8 + (lane & 3) * 2;
        cbase[(size_t)pr * Dx + col]           = rna_tf32(acc[j][0]);
        cbase[(size_t)pr * Dx + col + 1]       = rna_tf32(acc[j][1]);
        cbase[(size_t)(pr + 8) * Dx + col]     = rna_tf32(acc[j][2]);
        cbase[(size_t)(pr + 8) * Dx + col + 1] = rna_tf32(acc[j][3]);
    }
}

// ---------------- edge scores (tf32) ----------------
__device__ __forceinline__ void score_tile_tf(
    const float (*Qs)[FT_STRIDE], const float (*Ks)[FT_STRIDE],
    float acc[4][4], int lane, int warp_m, int warp_n)
{
    const int phase = lane >> 3;
    const int rli = lane & 7;
    const int a_roff = (phase & 1) * 8 + rli;
    const int a_koff = (phase >> 1) * 4;
    const int b_roff = (phase >> 1) * 8 + rli;
    const int b_koff = (phase & 1) * 4;

    #pragma unroll
    for (int kk = 0; kk < 64; kk += 8) {
        uint32_t aa[4];
        ldsm_x4(aa, (uint32_t)__cvta_generic_to_shared(
            &Qs[warp_m * 16 + a_roff][kk + a_koff]));
        #pragma unroll
        for (int p = 0; p < 2; p++) {
            uint32_t bb[4];
            ldsm_x4(bb, (uint32_t)__cvta_generic_to_shared(
                &Ks[warp_n * 32 + p * 16 + b_roff][kk + b_koff]));
            mma_tf32(acc[p * 2 + 0], aa, bb[0], bb[1]);
            mma_tf32(acc[p * 2 + 1], aa, bb[2], bb[3]);
        }
    }
}

__device__ __forceinline__ void pv_tile_tf(
    const float* __restrict__ P, int pstride, int pcol0,
    const float (*Vs)[FT_STRIDE],
    float acc[4][4], int lane, int warp_m, int warp_n)
{
    const int phase = lane >> 3;
    const int rli = lane & 7;
    const int a_roff = (phase & 1) * 8 + rli;
    const int a_koff = (phase >> 1) * 4;
    const int ck = lane & 3;
    const int nr = lane >> 2;

    #pragma unroll
    for (int kk = 0; kk < 64; kk += 8) {
        uint32_t aa[4];
        ldsm_x4(aa, (uint32_t)__cvta_generic_to_shared(
            P + (size_t)(warp_m * 16 + a_roff) * pstride + pcol0 + kk + a_koff));
        #pragma unroll
        for (int j = 0; j < 4; j++) {
            int n0 = warp_n * 32 + j * 8 + nr;
            uint32_t b0 = __float_as_uint(Vs[kk + ck][n0]);
            uint32_t b1 = __float_as_uint(Vs[kk + 4 + ck][n0]);
            mma_tf32(acc[j], aa, b0, b1);
        }
    }
}

__global__ void __launch_bounds__(256) edge_scores_tf(
    const float* __restrict__ q, const float* __restrict__ k,
    const int* __restrict__ amask, float* __restrict__ sedge)
{
    int kb = blockIdx.x, h = blockIdx.y;
    int e = blockIdx.z & 1, b = blockIdx.z >> 1;
    int qb = e ? (NBx - 1) : 0;
    __shared__ float Qs[64][FT_STRIDE];
    __shared__ float Ks[64][FT_STRIDE];
    int tid = threadIdx.x, lane = tid & 31, wid = tid >> 5;
    int warp_m = wid & 3, warp_n = wid >> 2;

    size_t qoff = ((size_t)b * Sx + qb * 64) * Dx + h * 64;
    size_t koff = ((size_t)b * Sx + kb * 64) * Dx + h * 64;
    load_ftile(Qs, q + qoff, Dx, tid);
    load_ftile(Ks, k + koff, Dx, tid);
    __syncthreads();

    float acc[4][4];
    #pragma unroll
    for (int j = 0; j < 4; j++) {
        acc[j][0] = 0.f; acc[j][1] = 0.f; acc[j][2] = 0.f; acc[j][3] = 0.f;
    }
    score_tile_tf(Qs, Ks, acc, lane, warp_m, warp_n);

    float* out = sedge + ((size_t)((b * NHx + h) * 2 + e)) * (64 * Sx);
    int r0 = warp_m * 16 + (lane >> 2);
    int mask_base = b * Sx + kb * 64;
    #pragma unroll
    for (int j = 0; j < 4; j++) {
        int ki = warp_n * 32 + j * 8 + (lane & 3) * 2;
        float m0 = (1.0f - (float)amask[mask_base + ki]) * -1e9f;
        float m1 = (1.0f - (float)amask[mask_base + ki + 1]) * -1e9f;
        out[(size_t)r0 * Sx + kb * 64 + ki]           = acc[j][0] * 0.125f + m0;
        out[(size_t)r0 * Sx + kb * 64 + ki + 1]       = acc[j][1] * 0.125f + m1;
        out[(size_t)(r0 + 8) * Sx + kb * 64 + ki]     = acc[j][2] * 0.125f + m0;
        out[(size_t)(r0 + 8) * Sx + kb * 64 + ki + 1] = acc[j][3] * 0.125f + m1;
    }
}

__global__ void softmax_rna_kernel(float* __restrict__ s, int L) {
    extern __shared__ float buf[];
    size_t base = (size_t)blockIdx.x * L;
    float m = -3.4e38f;
    for (int i = threadIdx.x; i < L; i += blockDim.x) {
        float x = s[base + i];
        buf[i] = x;
        m = fmaxf(m, x);
    }
    m = blk_max(m);
    float lsum = 0.f;
    for (int i = threadIdx.x; i < L; i += blockDim.x) {
        float e = fexp(buf[i] - m);
        buf[i] = e;
        lsum += e;
    }
    float sum = blk_sum(lsum);
    float inv = 1.f / sum;
    for (int i = threadIdx.x; i < L; i += blockDim.x)
        s[base + i] = rna_tf32(buf[i] * inv);
}

__global__ void __launch_bounds__(256) edge_pv_tf(
    const float* __restrict__ p, const float* __restrict__ v, float* __restrict__ ctx)
{
    int h = blockIdx.x;
    int e = blockIdx.y & 1, b = blockIdx.y >> 1;
    int chunk = blockIdx.z;
    int qb = e ? (NBx - 1) : 0;
    __shared__ float Ps[64][FT_STRIDE];
    __shared__ float Vs[64][FT_STRIDE];
    int tid = threadIdx.x, lane = tid & 31, wid = tid >> 5;
    int warp_m = wid & 3, warp_n = wid >> 2;

    const float* prow = p + ((size_t)((b * NHx + h) * 2 + e)) * (64 * Sx);

    float acc[4][4];
    #pragma unroll
    for (int j = 0; j < 4; j++) {
        acc[j][0] = 0.f; acc[j][1] = 0.f; acc[j][2] = 0.f; acc[j][3] = 0.f;
    }

    for (int c8 = 0; c8 < 8; c8++) {
        int kb = chunk * 8 + c8;
        size_t voff = ((size_t)b * Sx + kb * 64) * Dx + h * 64;
        __syncthreads();
        load_ftile(Ps, prow + kb * 64, Sx, tid);
        load_ftile(Vs, v + voff, Dx, tid);
        __syncthreads();
        pv_tile_tf(&Ps[0][0], FT_STRIDE, 0, Vs, acc, lane, warp_m, warp_n);
    }

    float* cbase = ctx + ((size_t)b * Sx + qb * 64) * Dx + h * 64;
    int r0 = warp_m * 16 + (lane >> 2);
    #pragma unroll
    for (int j = 0; j < 4; j++) {
        int col = warp_n * 32 + j * 8 + (lane & 3) * 2;
        atomicAdd(&cbase[(size_t)r0 * Dx + col],           acc[j][0]);
        atomicAdd(&cbase[(size_t)r0 * Dx + col + 1],       acc[j][1]);
        atomicAdd(&cbase[(size_t)(r0 + 8) * Dx + col],     acc[j][2]);
        atomicAdd(&cbase[(size_t)(r0 + 8) * Dx + col + 1], acc[j][3]);
    }
}

__global__ void zero_edge_ctx(float* __restrict__ ctx) {
    int i = blockIdx.x * 256 + threadIdx.x;
    if (i >= Bx * 2 * 64 * Dx) return;
    int col = i % Dx;
    int t = i / Dx;
    int row = t % 64;  t /= 64;
    int e = t & 1;
    int b = t >> 1;
    int blk = e ? (NBx - 1) : 0;
    ctx[((size_t)b * Sx + blk * 64 + row) * Dx + col] = 0.f;
}

// ---------------- pooler ----------------
__global__ void pooler_kernel(const float* __restrict__ h, const float* __restrict__ pw,
                              const float* __restrict__ pb, float* __restrict__ out) {
    int j = blockIdx.x * blockDim.x + threadIdx.x;
    int b = blockIdx.y;
    if (j >= Dx) return;
    const float* hr = h + (size_t)b * Sx * Dx;
    float acc = pb[j];
    for (int kI = 0; kI < Dx; kI++) acc += hr[kI] * pw[(size_t)kI * Dx + j];
    out[b * Dx + j] = tanhf(acc);
}

// ---------------- host launcher ----------------
extern "C" void kernel_launch(void* const* d_in, const int* in_sizes, int n_in,
                              void* d_out, int out_size) {
    const int*   input_ids = (const int*)d_in[0];
    const int*   attn_mask = (const int*)d_in[1];
    const int*   tok_type  = (const int*)d_in[2];
    const int*   rand_blk  = (const int*)d_in[3];
    const float* word_emb  = (const float*)d_in[4];
    const float* type_emb  = (const float*)d_in[5];
    const float* pos_emb   = (const float*)d_in[6];
    const float* emb_ln_s  = (const float*)d_in[7];
    const float* emb_ln_b  = (const float*)d_in[8];
    const float* Wq = (const float*)d_in[9];  const float* bq = (const float*)d_in[10];
    const float* Wk = (const float*)d_in[11]; const float* bk = (const float*)d_in[12];
    const float* Wv = (const float*)d_in[13]; const float* bv = (const float*)d_in[14];
    const float* Wo = (const float*)d_in[15]; const float* bo = (const float*)d_in[16];
    const float* ln1_s = (const float*)d_in[17]; const float* ln1_b = (const float*)d_in[18];
    const float* W1 = (const float*)d_in[19]; const float* b1 = (const float*)d_in[20];
    const float* W2 = (const float*)d_in[21]; const float* b2 = (const float*)d_in[22];
    const float* ln2_s = (const float*)d_in[23]; const float* ln2_b = (const float*)d_in[24];
    const float* pool_w = (const float*)d_in[25]; const float* pool_b = (const float*)d_in[26];
    float* out = (float*)d_out;

    float *p_h = 0, *p_res = 0, *p_ctx = 0, *p_ff = 0, *p_wt = 0, *p_sedge = 0;
    float *p_q = 0, *p_k = 0, *p_v = 0;
    cudaGetSymbolAddress((void**)&p_h,     g_h);
    cudaGetSymbolAddress((void**)&p_res,   g_res);
    cudaGetSymbolAddress((void**)&p_ctx,   g_ctx);
    cudaGetSymbolAddress((void**)&p_ff,    g_ff);
    cudaGetSymbolAddress((void**)&p_wt,    g_wt);
    cudaGetSymbolAddress((void**)&p_sedge, g_sedge);
    cudaGetSymbolAddress((void**)&p_q,     g_q);
    cudaGetSymbolAddress((void**)&p_k,     g_k);
    cudaGetSymbolAddress((void**)&p_v,     g_v);

    static bool init_done = false;
    static cudaStream_t s2;
    static cudaEvent_t evF0, evT, evF[2], evJ[2];
    if (!init_done) {
        cudaFuncSetAttribute(tf_gemm_kernel<0>, cudaFuncAttributeMaxDynamicSharedMemorySize, TF_SMEM_BYTES);
        cudaFuncSetAttribute(tf_gemm_kernel<3>, cudaFuncAttributeMaxDynamicSharedMemorySize, TF_SMEM_BYTES);
        cudaFuncSetAttribute(tf_qkv_kernel, cudaFuncAttributeMaxDynamicSharedMemorySize, TF_SMEM_BYTES);
        cudaFuncSetAttribute(mid_fused_kernel, cudaFuncAttributeMaxDynamicSharedMemorySize, MID_SMEM);
        cudaStreamCreateWithFlags(&s2, cudaStreamNonBlocking);
        cudaEventCreateWithFlags(&evF0, cudaEventDisableTiming);
        cudaEventCreateWithFlags(&evT,  cudaEventDisableTiming);
        cudaEventCreateWithFlags(&evF[0], cudaEventDisableTiming);
        cudaEventCreateWithFlags(&evF[1], cudaEventDisableTiming);
        cudaEventCreateWithFlags(&evJ[0], cudaEventDisableTiming);
        cudaEventCreateWithFlags(&evJ[1], cudaEventDisableTiming);
        init_done = true;
    }

    const int M = TOK;
    float* wt_qkv0 = p_wt;
    float* wt_wo   = p_wt + (size_t)6 * nDD;
    float* wt_w1   = p_wt + (size_t)8 * nDD;
    float* wt_w2   = p_wt + (size_t)8 * nDD + (size_t)2 * nDF;

    // fork: weight transposes on s2, overlapped with embed_ln on stream 0
    cudaEventRecord(evF0, 0);
    cudaStreamWaitEvent(s2, evF0, 0);
    trans_round_kernel<<<dim3(Dx/32, Dx/32, 2), dim3(32, 8), 0, s2>>>(Wq, wt_qkv0,           Dx, Dx, nDD, (size_t)3*nDD);
    trans_round_kernel<<<dim3(Dx/32, Dx/32, 2), dim3(32, 8), 0, s2>>>(Wk, wt_qkv0 + nDD,     Dx, Dx, nDD, (size_t)3*nDD);
    trans_round_kernel<<<dim3(Dx/32, Dx/32, 2), dim3(32, 8), 0, s2>>>(Wv, wt_qkv0 + 2*nDD,   Dx, Dx, nDD, (size_t)3*nDD);
    trans_round_kernel<<<dim3(Dx/32, Dx/32, 2), dim3(32, 8), 0, s2>>>(Wo, wt_wo,             Dx, Dx, nDD, (size_t)nDD);
    trans_round_kernel<<<dim3(FFx/32, Dx/32, 2), dim3(32, 8), 0, s2>>>(W1, wt_w1,            Dx, FFx, nDF, (size_t)nDF);
    trans_round_kernel<<<dim3(Dx/32, FFx/32, 2), dim3(32, 8), 0, s2>>>(W2, wt_w2,            FFx, Dx, nDF, (size_t)nDF);
    cudaEventRecord(evT, s2);

    embed_ln_kernel<<<TOK, 256>>>(input_ids, tok_type, word_emb, type_emb, pos_emb,
                                  emb_ln_s, emb_ln_b);
    cudaStreamWaitEvent(0, evT, 0);

    for (int l = 0; l < 2; l++) {
        const float* bql = bq + (size_t)l * Dx;
        const float* bkl = bk + (size_t)l * Dx;
        const float* bvl = bv + (size_t)l * Dx;
        const float* bol = bo + (size_t)l * Dx;
        const float* b1l = b1 + (size_t)l * FFx;
        const float* b2l = b2 + (size_t)l * Dx;
        const float* l1s = ln1_s + (size_t)l * Dx; const float* l1b = ln1_b + (size_t)l * Dx;
        const float* l2s = ln2_s + (size_t)l * Dx; const float* l2b = ln2_b + (size_t)l * Dx;

        tf_qkv_kernel<<<dim3(Dx / 128, M / 128, 3), 256, TF_SMEM_BYTES>>>(
            p_h, wt_qkv0 + (size_t)l * 3 * nDD, bql, bkl, bvl, p_q, p_k, p_v);

        // fork edge path onto s2
        cudaEventRecord(evF[l], 0);
        cudaStreamWaitEvent(s2, evF[l], 0);
        edge_scores_tf<<<dim3(NBx, NHx, Bx * 2), 256, 0, s2>>>(p_q, p_k, attn_mask, p_sedge);
        softmax_rna_kernel<<<Bx * NHx * 2 * BSx, 256, Sx * sizeof(float), s2>>>(p_sedge, Sx);
        zero_edge_ctx<<<(Bx * 2 * 64 * Dx + 255) / 256, 256, 0, s2>>>(p_ctx);
        edge_pv_tf<<<dim3(NHx, Bx * 2, 8), 256, 0, s2>>>(p_sedge, p_v, p_ctx);
        cudaEventRecord(evJ[l], s2);

        // mid path on stream 0 (async-pipelined)
        mid_fused_kernel<<<dim3(NMID, NHx, Bx), 256, MID_SMEM>>>(
            p_q, p_k, p_v, rand_blk, attn_mask, p_ctx);

        cudaStreamWaitEvent(0, evJ[l], 0);

        tf_gemm_kernel<0><<<dim3(Dx / 128, M / 128), 256, TF_SMEM_BYTES>>>(
            p_ctx, wt_wo + (size_t)l * nDD, bol, p_res, M, Dx, Dx);
        add_ln_kernel<<<TOK, 256>>>(p_h, p_res, l1s, l1b);

        tf_gemm_kernel<3><<<dim3(FFx / 128, M / 128), 256, TF_SMEM_BYTES>>>(
            p_h, wt_w1 + (size_t)l * nDF, b1l, p_ff, M, FFx, Dx);
        tf_gemm_kernel<0><<<dim3(Dx / 128, M / 128), 256, TF_SMEM_BYTES>>>(
            p_ff, wt_w2 + (size_t)l * nDF, b2l, p_res, M, Dx, FFx);
        add_ln_kernel<<<TOK, 256>>>(p_h, p_res, l2s, l2b);
    }

    pooler_kernel<<<dim3((Dx + 127) / 128, Bx), 128>>>(p_h, pool_w, pool_b, out);
}